// round 9
// baseline (speedup 1.0000x reference)
#include <cuda_runtime.h>
#include <cuda_bf16.h>

#define B_ 4
#define N_ 4096
#define D_ 256
#define MC 32                 // m-chunk
#define NITER (N_ / MC)       // 128

// Device-global scratch (allocation-free rule)
static __device__ __nv_bfloat16  g_vhi[B_ * N_ * D_];      // [b][n][d]
static __device__ __nv_bfloat16  g_vlo[B_ * N_ * D_];
static __device__ __nv_bfloat16  g_pthi[B_ * D_ * N_];     // [b][e][m]  (P transposed)
static __device__ __nv_bfloat16  g_ptlo[B_ * D_ * N_];

// ---------------- PTX helpers (baseline ISA only: sm_80-level) ----------------
__device__ __forceinline__ unsigned smem_u32(const void* p) {
    unsigned a;
    asm("{ .reg .u64 t; cvta.to.shared.u64 t, %1; cvt.u32.u64 %0, t; }" : "=r"(a) : "l"(p));
    return a;
}
__device__ __forceinline__ void cpa16(unsigned dst, const void* src) {
    asm volatile("cp.async.cg.shared.global [%0], [%1], 16;" :: "r"(dst), "l"(src) : "memory");
}
#define CP_COMMIT() asm volatile("cp.async.commit_group;" ::: "memory")
#define CP_WAIT1()  asm volatile("cp.async.wait_group 1;" ::: "memory")

__device__ __forceinline__ void ldm4(unsigned* r, unsigned addr) {
    asm volatile("ldmatrix.sync.aligned.m8n8.x4.shared.b16 {%0,%1,%2,%3}, [%4];"
                 : "=r"(r[0]), "=r"(r[1]), "=r"(r[2]), "=r"(r[3]) : "r"(addr));
}
__device__ __forceinline__ void mmab(float* d, const unsigned* a, unsigned b0, unsigned b1) {
    asm volatile(
        "mma.sync.aligned.m16n8k16.row.col.f32.bf16.bf16.f32 "
        "{%0,%1,%2,%3}, {%4,%5,%6,%7}, {%8,%9}, {%0,%1,%2,%3};"
        : "+f"(d[0]), "+f"(d[1]), "+f"(d[2]), "+f"(d[3])
        : "r"(a[0]), "r"(a[1]), "r"(a[2]), "r"(a[3]), "r"(b0), "r"(b1));
}
__device__ __forceinline__ void sts32(unsigned addr, unsigned v) {
    asm volatile("st.shared.u32 [%0], %1;" :: "r"(addr), "r"(v) : "memory");
}

// ---------------- prologue ----------------
__device__ __forceinline__ unsigned long long ffma2(unsigned long long a,
                                                    unsigned long long b,
                                                    unsigned long long c) {
    unsigned long long d;
    asm("fma.rn.f32x2 %0, %1, %2, %3;" : "=l"(d) : "l"(a), "l"(b), "l"(c));
    return d;
}
__device__ __forceinline__ unsigned long long dup2(float x) {
    unsigned long long d;
    asm("mov.b64 %0, {%1, %1};" : "=l"(d) : "f"(x));
    return d;
}
union V4 { float4 f; unsigned long long u[2]; };

// proj + transpose + bf16-split fused: writes g_pthi/g_ptlo[b][e][m] directly
__global__ __launch_bounds__(256, 2)
void proj_kernel(const float* __restrict__ val, const float* __restrict__ Wv) {
    __shared__ float As[64 * 36];
    __shared__ float Bs[32 * 68];
    __shared__ float Ts[64 * 65];
    const int t = threadIdx.x;
    const int tx = t & 15, ty = t >> 4;
    const int row0 = blockIdx.y * 64;
    const int e0 = blockIdx.x * 64;
    unsigned long long acc[4][2] = {};
    for (int k0 = 0; k0 < D_; k0 += 32) {
#pragma unroll
        for (int p = 0; p < 2; p++) {
            int idx = p * 256 + t, r = idx >> 3, q = idx & 7;
            *(float4*)&As[r * 36 + q * 4] =
                *(const float4*)&val[(size_t)(row0 + r) * D_ + k0 + q * 4];
        }
#pragma unroll
        for (int p = 0; p < 2; p++) {
            int idx = p * 256 + t, kr = idx >> 4, ec = idx & 15;
            *(float4*)&Bs[kr * 68 + ec * 4] =
                *(const float4*)&Wv[(k0 + kr) * D_ + e0 + ec * 4];
        }
        __syncthreads();
#pragma unroll 16
        for (int kk = 0; kk < 32; kk++) {
            V4 bv; bv.f = *(float4*)&Bs[kk * 68 + tx * 4];
#pragma unroll
            for (int i = 0; i < 4; i++) {
                unsigned long long a2 = dup2(As[(ty * 4 + i) * 36 + kk]);
                acc[i][0] = ffma2(a2, bv.u[0], acc[i][0]);
                acc[i][1] = ffma2(a2, bv.u[1], acc[i][1]);
            }
        }
        __syncthreads();
    }
    // transpose tile into Ts[e_local][m_local]
#pragma unroll
    for (int i = 0; i < 4; i++) {
        V4 o; o.u[0] = acc[i][0]; o.u[1] = acc[i][1];
        float v4[4] = {o.f.x, o.f.y, o.f.z, o.f.w};
#pragma unroll
        for (int q = 0; q < 4; q++)
            Ts[(tx * 4 + q) * 65 + ty * 4 + i] = v4[q];
    }
    __syncthreads();
    // write transposed bf16 hi/lo: thread -> (e_row = t>>2, 16 m's)
    {
        const int b = row0 >> 12, m0 = row0 & (N_ - 1);
        const int e_l = t >> 2, ms = (t & 3) * 16;
        unsigned hw[8], lw[8];
#pragma unroll
        for (int jj = 0; jj < 8; jj++) {
            float v0 = Ts[e_l * 65 + ms + 2 * jj];
            float v1 = Ts[e_l * 65 + ms + 2 * jj + 1];
            __nv_bfloat16 h0 = __float2bfloat16(v0), h1 = __float2bfloat16(v1);
            __nv_bfloat162 hp; hp.x = h0; hp.y = h1;
            __nv_bfloat162 lp;
            lp.x = __float2bfloat16(v0 - __bfloat162float(h0));
            lp.y = __float2bfloat16(v1 - __bfloat162float(h1));
            hw[jj] = *(unsigned*)&hp;
            lw[jj] = *(unsigned*)&lp;
        }
        size_t o = ((size_t)(b * D_ + e0 + e_l)) * N_ + m0 + ms;
        *(uint4*)(g_pthi + o)     = make_uint4(hw[0], hw[1], hw[2], hw[3]);
        *(uint4*)(g_pthi + o + 8) = make_uint4(hw[4], hw[5], hw[6], hw[7]);
        *(uint4*)(g_ptlo + o)     = make_uint4(lw[0], lw[1], lw[2], lw[3]);
        *(uint4*)(g_ptlo + o + 8) = make_uint4(lw[4], lw[5], lw[6], lw[7]);
    }
}

__global__ __launch_bounds__(256)
void split_val(const float* __restrict__ val) {
    size_t i = ((size_t)blockIdx.x * 256 + threadIdx.x) * 4;
    float4 v = *(const float4*)(val + i);
    float a[4] = {v.x, v.y, v.z, v.w};
#pragma unroll
    for (int k = 0; k < 4; k += 2) {
        __nv_bfloat16 h0 = __float2bfloat16(a[k]);
        __nv_bfloat16 h1 = __float2bfloat16(a[k + 1]);
        __nv_bfloat162 hp; hp.x = h0; hp.y = h1;
        __nv_bfloat162 lp;
        lp.x = __float2bfloat16(a[k] - __bfloat162float(h0));
        lp.y = __float2bfloat16(a[k + 1] - __bfloat162float(h1));
        *(__nv_bfloat162*)(g_vhi + i + k) = hp;
        *(__nv_bfloat162*)(g_vlo + i + k) = lp;
    }
}

// ---------------- main fused kernel (warp-level mma.sync / HMMA) ----------------
// SMEM layout (bytes)
#define OFF_VNH 0u         // Vn_hi 128 rows x 512B (swizzled)      65536
#define OFF_VNL 65536u     // Vn_lo                                  65536
#define OFF_VMH 131072u    // Vm_hi 32 x 512B                        16384
#define OFF_VML 147456u
#define OFF_PTH 163840u    // Pt_hi 256 rows x 80B (64B data + pad)  20480
#define OFF_PTL 184320u
#define OFF_EH  204800u    // E_hi 128 rows x 80B                    10240
#define OFF_EL  215040u
#define OFF_DS  225280u    // 128 floats
#define SMEM_SZ 225792u

__global__ __launch_bounds__(512, 1)
void prop_mma(const float* __restrict__ state, float* __restrict__ out) {
    extern __shared__ __align__(128) char sm[];
    const unsigned sb = smem_u32(sm);
    const int t = threadIdx.x;
    const int lane = t & 31, w = t >> 5;
    // Phase A layout: 8 rg (m16) x 2 ch (n16)
    const int rg = w >> 1, ch = w & 1;
    const int RG = rg * 16;
    // Phase B layout: 4 rg2 (m32) x 4 ch2 (e64)
    const int rg2 = w >> 2, ch2 = w & 3;
    const int RG2 = rg2 * 32;
    const int b = blockIdx.y;
    const int n0 = blockIdx.x * 128;

    const __nv_bfloat16* vh  = g_vhi  + (size_t)b * N_ * D_;
    const __nv_bfloat16* vl  = g_vlo  + (size_t)b * N_ * D_;
    const __nv_bfloat16* pth = g_pthi + (size_t)b * D_ * N_;
    const __nv_bfloat16* ptl = g_ptlo + (size_t)b * D_ * N_;
    const float* stb = state + b * N_;

    float* ds_sm = (float*)(sm + OFF_DS);
    if (t < 128) ds_sm[t] = 0.f;

    // ---- Vn (persistent) + Vm(0) : commit group 0 ----
#pragma unroll
    for (int j = 0; j < 8; j++) {
        int idx = j * 512 + t, row = idx >> 5, kc = idx & 31;
        unsigned swz = (unsigned)(row * 512) + (((unsigned)kc * 16) ^ (((unsigned)row & 7) << 4));
        cpa16(sb + OFF_VNH + swz, vh + (size_t)(n0 + row) * D_ + kc * 8);
        cpa16(sb + OFF_VNL + swz, vl + (size_t)(n0 + row) * D_ + kc * 8);
    }
#pragma unroll
    for (int j = 0; j < 2; j++) {
        int idx = j * 512 + t, row = idx >> 5, kc = idx & 31;
        unsigned swz = (unsigned)(row * 512) + (((unsigned)kc * 16) ^ (((unsigned)row & 7) << 4));
        cpa16(sb + OFF_VMH + swz, vh + (size_t)row * D_ + kc * 8);
        cpa16(sb + OFF_VML + swz, vl + (size_t)row * D_ + kc * 8);
    }
    CP_COMMIT();
    // ---- Pt(0) : commit group 1 ----
#pragma unroll
    for (int j = 0; j < 2; j++) {
        int idx = j * 512 + t, row = idx >> 2, kc = idx & 3;
        unsigned o = (unsigned)(row * 80 + kc * 16);
        cpa16(sb + OFF_PTH + o, pth + (size_t)row * N_ + kc * 8);
        cpa16(sb + OFF_PTL + o, ptl + (size_t)row * N_ + kc * 8);
    }
    CP_COMMIT();

    float accD[64];
#pragma unroll
    for (int q = 0; q < 64; q++) accD[q] = 0.f;
    float ds0 = 0.f, ds1 = 0.f;

    // Phase A fragment addresses
    const unsigned aRow = RG + (lane & 15);
    const unsigned aK   = ((unsigned)lane >> 4) * 16;
    const unsigned aSw  = (aRow & 7) << 4;
    const unsigned aBase = aRow * 512;
    const unsigned bRow = (unsigned)(ch * 16) + (((unsigned)lane >> 4) << 3) + (lane & 7);
    const unsigned bK   = (((unsigned)lane >> 3) & 1) * 16;
    const unsigned bSw  = (bRow & 7) << 4;
    const unsigned bBase = bRow * 512;
    // Phase B fragment addresses
    const unsigned eB0 = (unsigned)(RG2 + (lane & 15)) * 80 + ((unsigned)lane >> 4) * 16;
    const unsigned eB1 = eB0 + 16 * 80;
    const unsigned pB  = ((unsigned)(ch2 * 64) + (((unsigned)lane >> 4) << 3) + (lane & 7)) * 80
                       + (((unsigned)lane >> 3) & 1) * 16;
    const int r = lane >> 2, c = (lane & 3) * 2;
    const int Cb0 = ch * 16 + c;   // epilogue columns (tl=0: Cb0, tl=1: Cb0+8)

#pragma unroll 1
    for (int i = 0; i < NITER; i++) {
        const int m0 = i * MC;
        CP_WAIT1();            // Vm(i) ready (and Vn on i==0)
        __syncthreads();

        // early state loads (consumed in epilogue; latency hides under Phase A)
        float sc[4];
        sc[0] = __ldg(stb + m0 + Cb0);
        sc[1] = __ldg(stb + m0 + Cb0 + 1);
        sc[2] = __ldg(stb + m0 + Cb0 + 8);
        sc[3] = __ldg(stb + m0 + Cb0 + 9);

        // -------- Phase A: S[128x32] = Vn . Vm^T, split-bf16 (hh+hl+lh) --------
        float accS[8];
#pragma unroll
        for (int q = 0; q < 8; q++) accS[q] = 0.f;
#pragma unroll
        for (int ks = 0; ks < 16; ks++) {
            unsigned ah[4], al[4], bh[4], bl[4];
            unsigned ka = ((unsigned)(ks * 32) + aK) ^ aSw;
            ldm4(ah, sb + OFF_VNH + aBase + ka);
            ldm4(al, sb + OFF_VNL + aBase + ka);
            unsigned kb = ((unsigned)(ks * 32) + bK) ^ bSw;
            ldm4(bh, sb + OFF_VMH + bBase + kb);
            ldm4(bl, sb + OFF_VML + bBase + kb);
            // interleaved: dependency distance 2 on each accumulator
            mmab(accS,     ah, bh[0], bh[1]);
            mmab(accS + 4, ah, bh[2], bh[3]);
            mmab(accS,     ah, bl[0], bl[1]);
            mmab(accS + 4, ah, bl[2], bl[3]);
            mmab(accS,     al, bh[0], bh[1]);
            mmab(accS + 4, al, bh[2], bh[3]);
        }
        __syncthreads();       // all Vm reads done

        // prefetch Vm(i+1) (clamped on last iter to keep group counts uniform)
        const int m1 = (i < NITER - 1) ? m0 + MC : 0;
#pragma unroll
        for (int j = 0; j < 2; j++) {
            int idx = j * 512 + t, row = idx >> 5, kc = idx & 31;
            unsigned swz = (unsigned)(row * 512) + (((unsigned)kc * 16) ^ (((unsigned)row & 7) << 4));
            cpa16(sb + OFF_VMH + swz, vh + (size_t)(m1 + row) * D_ + kc * 8);
            cpa16(sb + OFF_VML + swz, vl + (size_t)(m1 + row) * D_ + kc * 8);
        }
        CP_COMMIT();

        // -------- epilogue: softsign, delta_state, E hi/lo -> SMEM --------
#pragma unroll
        for (int tl = 0; tl < 2; tl++) {
            int Cb = Cb0 + tl * 8;
            float s0 = accS[tl * 4 + 0], s1 = accS[tl * 4 + 1];
            float s2 = accS[tl * 4 + 2], s3 = accS[tl * 4 + 3];
            float e0 = __fdividef(s0, 1.f + fabsf(s0));
            float e1 = __fdividef(s1, 1.f + fabsf(s1));
            float e2 = __fdividef(s2, 1.f + fabsf(s2));
            float e3 = __fdividef(s3, 1.f + fabsf(s3));
            ds0 += e0 * sc[tl * 2] + e1 * sc[tl * 2 + 1];
            ds1 += e2 * sc[tl * 2] + e3 * sc[tl * 2 + 1];
            __nv_bfloat16 h0 = __float2bfloat16(e0), h1 = __float2bfloat16(e1);
            __nv_bfloat16 h2 = __float2bfloat16(e2), h3 = __float2bfloat16(e3);
            __nv_bfloat162 hp01; hp01.x = h0; hp01.y = h1;
            __nv_bfloat162 hp23; hp23.x = h2; hp23.y = h3;
            __nv_bfloat162 lp01, lp23;
            lp01.x = __float2bfloat16(e0 - __bfloat162float(h0));
            lp01.y = __float2bfloat16(e1 - __bfloat162float(h1));
            lp23.x = __float2bfloat16(e2 - __bfloat162float(h2));
            lp23.y = __float2bfloat16(e3 - __bfloat162float(h3));
            unsigned o0 = (unsigned)((RG + r) * 80 + Cb * 2);
            unsigned o1 = o0 + 8 * 80;
            sts32(sb + OFF_EH + o0, *(unsigned*)&hp01);
            sts32(sb + OFF_EL + o0, *(unsigned*)&lp01);
            sts32(sb + OFF_EH + o1, *(unsigned*)&hp23);
            sts32(sb + OFF_EL + o1, *(unsigned*)&lp23);
        }
        CP_WAIT1();            // Pt(i) ready
        __syncthreads();       // E + Pt visible

        // -------- Phase B: dval[128x256] += E . Pt^T, split-bf16, 4rg2 x 4ch2 --------
#pragma unroll
        for (int ks = 0; ks < 2; ks++) {
            unsigned eh0[4], el0[4], eh1[4], el1[4];
            ldm4(eh0, sb + OFF_EH + eB0 + ks * 32);
            ldm4(el0, sb + OFF_EL + eB0 + ks * 32);
            ldm4(eh1, sb + OFF_EH + eB1 + ks * 32);
            ldm4(el1, sb + OFF_EL + eB1 + ks * 32);
#pragma unroll
            for (int g = 0; g < 4; g++) {
                unsigned ph[4], pl[4];
                unsigned po = pB + (unsigned)(g * 16 * 80 + ks * 32);
                ldm4(ph, sb + OFF_PTH + po);
                ldm4(pl, sb + OFF_PTL + po);
                float* d00 = accD + ((0 * 4 + g) * 2 + 0) * 4;
                float* d01 = accD + ((0 * 4 + g) * 2 + 1) * 4;
                float* d10 = accD + ((1 * 4 + g) * 2 + 0) * 4;
                float* d11 = accD + ((1 * 4 + g) * 2 + 1) * 4;
                // interleaved across 4 independent accumulators
                mmab(d00, eh0, ph[0], ph[1]);
                mmab(d10, eh1, ph[0], ph[1]);
                mmab(d01, eh0, ph[2], ph[3]);
                mmab(d11, eh1, ph[2], ph[3]);
                mmab(d00, eh0, pl[0], pl[1]);
                mmab(d10, eh1, pl[0], pl[1]);
                mmab(d01, eh0, pl[2], pl[3]);
                mmab(d11, eh1, pl[2], pl[3]);
                mmab(d00, el0, ph[0], ph[1]);
                mmab(d10, el1, ph[0], ph[1]);
                mmab(d01, el0, ph[2], ph[3]);
                mmab(d11, el1, ph[2], ph[3]);
            }
        }
        __syncthreads();       // all Pt + E reads done

        // prefetch Pt(i+1) (clamped)
#pragma unroll
        for (int j = 0; j < 2; j++) {
            int idx = j * 512 + t, row = idx >> 2, kc = idx & 3;
            unsigned o = (unsigned)(row * 80 + kc * 16);
            cpa16(sb + OFF_PTH + o, pth + (size_t)row * N_ + m1 + kc * 8);
            cpa16(sb + OFF_PTL + o, ptl + (size_t)row * N_ + m1 + kc * 8);
        }
        CP_COMMIT();
    }

    // -------- write delta_val (Phase B layout) --------
    float* dvb = out + B_ * N_ + ((size_t)(b * N_ + n0)) * D_;
#pragma unroll
    for (int s = 0; s < 2; s++) {
#pragma unroll
        for (int g = 0; g < 4; g++) {
#pragma unroll
            for (int h2 = 0; h2 < 2; h2++) {
                int row = RG2 + s * 16 + r;
                int col = ch2 * 64 + g * 16 + h2 * 8 + c;
                const float* d = accD + ((s * 4 + g) * 2 + h2) * 4;
                float2 lo; lo.x = d[0]; lo.y = d[1];
                float2 hi; hi.x = d[2]; hi.y = d[3];
                *(float2*)(dvb + (size_t)row * D_ + col) = lo;
                *(float2*)(dvb + (size_t)(row + 8) * D_ + col) = hi;
            }
        }
    }

    // -------- reduce & write delta_state (Phase A layout) --------
    ds0 += __shfl_xor_sync(0xffffffffu, ds0, 1);
    ds0 += __shfl_xor_sync(0xffffffffu, ds0, 2);
    ds1 += __shfl_xor_sync(0xffffffffu, ds1, 1);
    ds1 += __shfl_xor_sync(0xffffffffu, ds1, 2);
    if ((lane & 3) == 0) {
        atomicAdd(ds_sm + RG + r, ds0);
        atomicAdd(ds_sm + RG + r + 8, ds1);
    }
    __syncthreads();
    if (t < 128) out[b * N_ + n0 + t] = ds_sm[t];
}

extern "C" void kernel_launch(void* const* d_in, const int* in_sizes, int n_in,
                              void* d_out, int out_size) {
    const float* val   = (const float*)d_in[0];  // [B, N, D]
    const float* state = (const float*)d_in[1];  // [B, N]
    const float* Wv    = (const float*)d_in[2];  // [D, D]
    float* out = (float*)d_out;                  // [B*N] delta_state, [B*N*D] delta_val
    (void)in_sizes; (void)n_in; (void)out_size;

    cudaFuncSetAttribute(prop_mma, cudaFuncAttributeMaxDynamicSharedMemorySize, SMEM_SZ);

    split_val<<<(B_ * N_ * D_) / 1024, 256>>>(val);
    proj_kernel<<<dim3(D_ / 64, (B_ * N_) / 64), 256>>>(val, Wv);
    prop_mma<<<dim3(N_ / 128, B_), 512, SMEM_SZ>>>(state, out);
}

// round 10
// speedup vs baseline: 1.4239x; 1.4239x over previous
#include <cuda_runtime.h>
#include <cuda_fp16.h>

#define B_ 4
#define N_ 4096
#define D_ 256
#define MC 32                 // m-chunk
#define NITER (N_ / MC)       // 128

// Device-global scratch (allocation-free rule)
static __device__ __half  g_vhi[B_ * N_ * D_];      // [b][n][d] fp16 hi
static __device__ __half  g_vlo[B_ * N_ * D_];      // fp16 lo residual
static __device__ __half  g_pthi[B_ * D_ * N_];     // [b][e][m]  P transposed, fp16

// ---------------- PTX helpers (baseline ISA only: sm_80-level) ----------------
__device__ __forceinline__ unsigned smem_u32(const void* p) {
    unsigned a;
    asm("{ .reg .u64 t; cvta.to.shared.u64 t, %1; cvt.u32.u64 %0, t; }" : "=r"(a) : "l"(p));
    return a;
}
__device__ __forceinline__ void cpa16(unsigned dst, const void* src) {
    asm volatile("cp.async.cg.shared.global [%0], [%1], 16;" :: "r"(dst), "l"(src) : "memory");
}
#define CP_COMMIT() asm volatile("cp.async.commit_group;" ::: "memory")
#define CP_WAIT0()  asm volatile("cp.async.wait_group 0;" ::: "memory")
#define CP_WAIT1()  asm volatile("cp.async.wait_group 1;" ::: "memory")

__device__ __forceinline__ void ldm4(unsigned* r, unsigned addr) {
    asm volatile("ldmatrix.sync.aligned.m8n8.x4.shared.b16 {%0,%1,%2,%3}, [%4];"
                 : "=r"(r[0]), "=r"(r[1]), "=r"(r[2]), "=r"(r[3]) : "r"(addr));
}
__device__ __forceinline__ void mmah(float* d, const unsigned* a, unsigned b0, unsigned b1) {
    asm volatile(
        "mma.sync.aligned.m16n8k16.row.col.f32.f16.f16.f32 "
        "{%0,%1,%2,%3}, {%4,%5,%6,%7}, {%8,%9}, {%0,%1,%2,%3};"
        : "+f"(d[0]), "+f"(d[1]), "+f"(d[2]), "+f"(d[3])
        : "r"(a[0]), "r"(a[1]), "r"(a[2]), "r"(a[3]), "r"(b0), "r"(b1));
}
__device__ __forceinline__ void sts32(unsigned addr, unsigned v) {
    asm volatile("st.shared.u32 [%0], %1;" :: "r"(addr), "r"(v) : "memory");
}
__device__ __forceinline__ unsigned pack_h2(float x, float y) {
    __half2 h; h.x = __float2half_rn(x); h.y = __float2half_rn(y);
    return *(unsigned*)&h;
}

// ---------------- prologue ----------------
__device__ __forceinline__ unsigned long long ffma2(unsigned long long a,
                                                    unsigned long long b,
                                                    unsigned long long c) {
    unsigned long long d;
    asm("fma.rn.f32x2 %0, %1, %2, %3;" : "=l"(d) : "l"(a), "l"(b), "l"(c));
    return d;
}
__device__ __forceinline__ unsigned long long dup2(float x) {
    unsigned long long d;
    asm("mov.b64 %0, {%1, %1};" : "=l"(d) : "f"(x));
    return d;
}
union V4 { float4 f; unsigned long long u[2]; };

// proj + transpose + fp16 convert fused: writes g_pthi[b][e][m] directly
__global__ __launch_bounds__(256, 2)
void proj_kernel(const float* __restrict__ val, const float* __restrict__ Wv) {
    __shared__ float As[64 * 36];
    __shared__ float Bs[32 * 68];
    __shared__ float Ts[64 * 65];
    const int t = threadIdx.x;
    const int tx = t & 15, ty = t >> 4;
    const int row0 = blockIdx.y * 64;
    const int e0 = blockIdx.x * 64;
    unsigned long long acc[4][2] = {};
    for (int k0 = 0; k0 < D_; k0 += 32) {
#pragma unroll
        for (int p = 0; p < 2; p++) {
            int idx = p * 256 + t, r = idx >> 3, q = idx & 7;
            *(float4*)&As[r * 36 + q * 4] =
                *(const float4*)&val[(size_t)(row0 + r) * D_ + k0 + q * 4];
        }
#pragma unroll
        for (int p = 0; p < 2; p++) {
            int idx = p * 256 + t, kr = idx >> 4, ec = idx & 15;
            *(float4*)&Bs[kr * 68 + ec * 4] =
                *(const float4*)&Wv[(k0 + kr) * D_ + e0 + ec * 4];
        }
        __syncthreads();
#pragma unroll 16
        for (int kk = 0; kk < 32; kk++) {
            V4 bv; bv.f = *(float4*)&Bs[kk * 68 + tx * 4];
#pragma unroll
            for (int i = 0; i < 4; i++) {
                unsigned long long a2 = dup2(As[(ty * 4 + i) * 36 + kk]);
                acc[i][0] = ffma2(a2, bv.u[0], acc[i][0]);
                acc[i][1] = ffma2(a2, bv.u[1], acc[i][1]);
            }
        }
        __syncthreads();
    }
#pragma unroll
    for (int i = 0; i < 4; i++) {
        V4 o; o.u[0] = acc[i][0]; o.u[1] = acc[i][1];
        float v4[4] = {o.f.x, o.f.y, o.f.z, o.f.w};
#pragma unroll
        for (int q = 0; q < 4; q++)
            Ts[(tx * 4 + q) * 65 + ty * 4 + i] = v4[q];
    }
    __syncthreads();
    {
        const int b = row0 >> 12, m0l = row0 & (N_ - 1);
        const int e_l = t >> 2, ms = (t & 3) * 16;
        unsigned hw[8];
#pragma unroll
        for (int jj = 0; jj < 8; jj++)
            hw[jj] = pack_h2(Ts[e_l * 65 + ms + 2 * jj], Ts[e_l * 65 + ms + 2 * jj + 1]);
        size_t o = ((size_t)(b * D_ + e0 + e_l)) * N_ + m0l + ms;
        *(uint4*)(g_pthi + o)     = make_uint4(hw[0], hw[1], hw[2], hw[3]);
        *(uint4*)(g_pthi + o + 8) = make_uint4(hw[4], hw[5], hw[6], hw[7]);
    }
}

__global__ __launch_bounds__(256)
void split_val(const float* __restrict__ val) {
    size_t i = ((size_t)blockIdx.x * 256 + threadIdx.x) * 4;
    float4 v = *(const float4*)(val + i);
    float a[4] = {v.x, v.y, v.z, v.w};
#pragma unroll
    for (int k = 0; k < 4; k += 2) {
        __half h0 = __float2half_rn(a[k]);
        __half h1 = __float2half_rn(a[k + 1]);
        __half2 hp; hp.x = h0; hp.y = h1;
        __half2 lp;
        lp.x = __float2half_rn(a[k] - __half2float(h0));
        lp.y = __float2half_rn(a[k + 1] - __half2float(h1));
        *(__half2*)(g_vhi + i + k) = hp;
        *(__half2*)(g_vlo + i + k) = lp;
    }
}

// ---------------- main fused kernel ----------------
// SMEM layout (bytes)
#define OFF_VNH 0u         // Vn_hi 128 rows x 512B (swizzled)   65536
#define OFF_VNL 65536u     // Vn_lo                               65536
#define OFF_VM  131072u    // Vm double buffer: 2 x (h 16K + l 16K) = 65536
#define OFF_PT  196608u    // Pt_hi 256 rows x 80B                20480
#define OFF_EH  217088u    // E_hi 128 rows x 80B                 10240
#define OFF_DS  227328u    // 128 floats
#define SMEM_SZ 227840u

__global__ __launch_bounds__(512, 1)
void prop_mma(const float* __restrict__ state, float* __restrict__ out) {
    extern __shared__ __align__(128) char sm[];
    const unsigned sb = smem_u32(sm);
    const int t = threadIdx.x;
    const int lane = t & 31, w = t >> 5;
    // Phase A layout: 8 rg (m16) x 2 ch (n16)
    const int rg = w >> 1, ch = w & 1;
    const int RG = rg * 16;
    // Phase B layout: 4 rg2 (m32) x 4 ch2 (e64)
    const int rg2 = w >> 2, ch2 = w & 3;
    const int RG2 = rg2 * 32;
    const int b = blockIdx.y;
    const int n0 = blockIdx.x * 128;

    const __half* vh  = g_vhi  + (size_t)b * N_ * D_;
    const __half* vl  = g_vlo  + (size_t)b * N_ * D_;
    const __half* pth = g_pthi + (size_t)b * D_ * N_;
    const float* stb = state + b * N_;

    float* ds_sm = (float*)(sm + OFF_DS);
    if (t < 128) ds_sm[t] = 0.f;

    // ---- prologue loads: Vn (persistent) + Vm[0] into buf0 : one commit group ----
#pragma unroll
    for (int j = 0; j < 8; j++) {
        int idx = j * 512 + t, row = idx >> 5, kc = idx & 31;
        unsigned swz = (unsigned)(row * 512) + (((unsigned)kc * 16) ^ (((unsigned)row & 7) << 4));
        cpa16(sb + OFF_VNH + swz, vh + (size_t)(n0 + row) * D_ + kc * 8);
        cpa16(sb + OFF_VNL + swz, vl + (size_t)(n0 + row) * D_ + kc * 8);
    }
    {
        int idx = t, row = idx >> 4, kc2 = idx & 15;   // 512 thr: 32 rows x 16 of 32 kc
#pragma unroll
        for (int j = 0; j < 2; j++) {
            int kc = kc2 * 2 + j;
            unsigned swz = (unsigned)(row * 512) + (((unsigned)kc * 16) ^ (((unsigned)row & 7) << 4));
            cpa16(sb + OFF_VM + swz, vh + (size_t)row * D_ + kc * 8);
            cpa16(sb + OFF_VM + 16384u + swz, vl + (size_t)row * D_ + kc * 8);
        }
    }
    CP_COMMIT();

    float accD[64];
#pragma unroll
    for (int q = 0; q < 64; q++) accD[q] = 0.f;
    float ds0 = 0.f, ds1 = 0.f;

    // Phase A fragment addresses
    const unsigned aRow = RG + (lane & 15);
    const unsigned aK   = ((unsigned)lane >> 4) * 16;
    const unsigned aSw  = (aRow & 7) << 4;
    const unsigned aBase = aRow * 512;
    const unsigned bRow = (unsigned)(ch * 16) + (((unsigned)lane >> 4) << 3) + (lane & 7);
    const unsigned bK   = (((unsigned)lane >> 3) & 1) * 16;
    const unsigned bSw  = (bRow & 7) << 4;
    const unsigned bBase = bRow * 512;
    // Phase B fragment addresses
    const unsigned eB0 = (unsigned)(RG2 + (lane & 15)) * 80 + ((unsigned)lane >> 4) * 16;
    const unsigned eB1 = eB0 + 16 * 80;
    const unsigned pB  = ((unsigned)(ch2 * 64) + (((unsigned)lane >> 4) << 3) + (lane & 7)) * 80
                       + (((unsigned)lane >> 3) & 1) * 16;
    const int r = lane >> 2, c = (lane & 3) * 2;
    const int Cb0 = ch * 16 + c;

#pragma unroll 1
    for (int i = 0; i < NITER; i++) {
        const int m0 = i * MC;
        CP_WAIT0();            // Vm[i] (own groups) complete
        __syncthreads();       // b1: Vm[i] visible; Phase B(i-1) done -> E, Pt free

        // issue Vm[i+1] into the other buffer (clamped on last iter)
        const int m1 = (i < NITER - 1) ? m0 + MC : 0;
        {
            unsigned nb = sb + OFF_VM + (unsigned)((i + 1) & 1) * 32768u;
            int row = t >> 4, kc2 = t & 15;
#pragma unroll
            for (int j = 0; j < 2; j++) {
                int kc = kc2 * 2 + j;
                unsigned swz = (unsigned)(row * 512) + (((unsigned)kc * 16) ^ (((unsigned)row & 7) << 4));
                cpa16(nb + swz, vh + (size_t)(m1 + row) * D_ + kc * 8);
                cpa16(nb + 16384u + swz, vl + (size_t)(m1 + row) * D_ + kc * 8);
            }
            CP_COMMIT();
        }
        // issue Pt[i]  (single buffer; safe: Phase B(i-1) done at b1)
#pragma unroll
        for (int j = 0; j < 2; j++) {
            int idx = j * 512 + t, row = idx >> 2, kc = idx & 3;
            unsigned o = (unsigned)(row * 80 + kc * 16);
            cpa16(sb + OFF_PT + o, pth + (size_t)row * N_ + m0 + kc * 8);
        }
        CP_COMMIT();

        // early state loads (latency hides under Phase A)
        float sc[4];
        sc[0] = __ldg(stb + m0 + Cb0);
        sc[1] = __ldg(stb + m0 + Cb0 + 1);
        sc[2] = __ldg(stb + m0 + Cb0 + 8);
        sc[3] = __ldg(stb + m0 + Cb0 + 9);

        // -------- Phase A: S[128x32] = Vn . Vm^T, fp16 3-term (hh+lh+hl) --------
        const unsigned vmb = sb + OFF_VM + (unsigned)(i & 1) * 32768u;
        float accS[8];
#pragma unroll
        for (int q = 0; q < 8; q++) accS[q] = 0.f;
#pragma unroll
        for (int ks = 0; ks < 16; ks++) {
            unsigned ah[4], al[4], bh[4], bl[4];
            unsigned ka = ((unsigned)(ks * 32) + aK) ^ aSw;
            ldm4(ah, sb + OFF_VNH + aBase + ka);
            ldm4(al, sb + OFF_VNL + aBase + ka);
            unsigned kb = ((unsigned)(ks * 32) + bK) ^ bSw;
            ldm4(bh, vmb + bBase + kb);
            ldm4(bl, vmb + 16384u + bBase + kb);
            mmah(accS,     ah, bh[0], bh[1]);
            mmah(accS + 4, ah, bh[2], bh[3]);
            mmah(accS,     al, bh[0], bh[1]);
            mmah(accS + 4, al, bh[2], bh[3]);
            mmah(accS,     ah, bl[0], bl[1]);
            mmah(accS + 4, ah, bl[2], bl[3]);
        }

        // -------- epilogue: softsign, delta_state, E (fp16, single) -> SMEM --------
#pragma unroll
        for (int tl = 0; tl < 2; tl++) {
            int Cb = Cb0 + tl * 8;
            float s0 = accS[tl * 4 + 0], s1 = accS[tl * 4 + 1];
            float s2 = accS[tl * 4 + 2], s3 = accS[tl * 4 + 3];
            float e0 = __fdividef(s0, 1.f + fabsf(s0));
            float e1 = __fdividef(s1, 1.f + fabsf(s1));
            float e2 = __fdividef(s2, 1.f + fabsf(s2));
            float e3 = __fdividef(s3, 1.f + fabsf(s3));
            ds0 += e0 * sc[tl * 2] + e1 * sc[tl * 2 + 1];
            ds1 += e2 * sc[tl * 2] + e3 * sc[tl * 2 + 1];
            unsigned o0 = (unsigned)((RG + r) * 80 + Cb * 2);
            sts32(sb + OFF_EH + o0, pack_h2(e0, e1));
            sts32(sb + OFF_EH + o0 + 8 * 80, pack_h2(e2, e3));
        }
        CP_WAIT1();            // Pt[i] done (Vm[i+1] still in flight)
        __syncthreads();       // b2: E + Pt visible

        // -------- Phase B: dval[128x256] += E . Pt^T, fp16 1-term --------
#pragma unroll
        for (int ks = 0; ks < 2; ks++) {
            unsigned eh0[4], eh1[4];
            ldm4(eh0, sb + OFF_EH + eB0 + ks * 32);
            ldm4(eh1, sb + OFF_EH + eB1 + ks * 32);
#pragma unroll
            for (int g = 0; g < 4; g++) {
                unsigned ph[4];
                unsigned po = pB + (unsigned)(g * 16 * 80 + ks * 32);
                ldm4(ph, sb + OFF_PT + po);
                float* d00 = accD + ((0 * 4 + g) * 2 + 0) * 4;
                float* d01 = accD + ((0 * 4 + g) * 2 + 1) * 4;
                float* d10 = accD + ((1 * 4 + g) * 2 + 0) * 4;
                float* d11 = accD + ((1 * 4 + g) * 2 + 1) * 4;
                mmah(d00, eh0, ph[0], ph[1]);
                mmah(d10, eh1, ph[0], ph[1]);
                mmah(d01, eh0, ph[2], ph[3]);
                mmah(d11, eh1, ph[2], ph[3]);
            }
        }
    }

    // -------- write delta_val (Phase B layout) --------
    float* dvb = out + B_ * N_ + ((size_t)(b * N_ + n0)) * D_;
#pragma unroll
    for (int s = 0; s < 2; s++) {
#pragma unroll
        for (int g = 0; g < 4; g++) {
#pragma unroll
            for (int h2 = 0; h2 < 2; h2++) {
                int row = RG2 + s * 16 + r;
                int col = ch2 * 64 + g * 16 + h2 * 8 + c;
                const float* d = accD + ((s * 4 + g) * 2 + h2) * 4;
                float2 lo; lo.x = d[0]; lo.y = d[1];
                float2 hi; hi.x = d[2]; hi.y = d[3];
                *(float2*)(dvb + (size_t)row * D_ + col) = lo;
                *(float2*)(dvb + (size_t)(row + 8) * D_ + col) = hi;
            }
        }
    }

    // -------- reduce & write delta_state (Phase A layout) --------
    ds0 += __shfl_xor_sync(0xffffffffu, ds0, 1);
    ds0 += __shfl_xor_sync(0xffffffffu, ds0, 2);
    ds1 += __shfl_xor_sync(0xffffffffu, ds1, 1);
    ds1 += __shfl_xor_sync(0xffffffffu, ds1, 2);
    if ((lane & 3) == 0) {
        atomicAdd(ds_sm + RG + r, ds0);
        atomicAdd(ds_sm + RG + r + 8, ds1);
    }
    __syncthreads();
    if (t < 128) out[b * N_ + n0 + t] = ds_sm[t];
}

extern "C" void kernel_launch(void* const* d_in, const int* in_sizes, int n_in,
                              void* d_out, int out_size) {
    const float* val   = (const float*)d_in[0];  // [B, N, D]
    const float* state = (const float*)d_in[1];  // [B, N]
    const float* Wv    = (const float*)d_in[2];  // [D, D]
    float* out = (float*)d_out;                  // [B*N] delta_state, [B*N*D] delta_val
    (void)in_sizes; (void)n_in; (void)out_size;

    cudaFuncSetAttribute(prop_mma, cudaFuncAttributeMaxDynamicSharedMemorySize, SMEM_SZ);

    split_val<<<(B_ * N_ * D_) / 1024, 256>>>(val);
    proj_kernel<<<dim3(D_ / 64, (B_ * N_) / 64), 256>>>(val, Wv);
    prop_mma<<<dim3(N_ / 128, B_), 512, SMEM_SZ>>>(state, out);
}

// round 11
// speedup vs baseline: 1.7015x; 1.1949x over previous
#include <cuda_runtime.h>
#include <cuda_fp16.h>

#define B_ 4
#define N_ 4096
#define D_ 256
#define MC 32                 // m-chunk
#define NITER (N_ / MC)       // 128

// Device-global scratch (allocation-free rule)
static __device__ __half  g_vhi[B_ * N_ * D_];      // [b][n][d] fp16 hi
static __device__ __half  g_vlo[B_ * N_ * D_];      // fp16 lo residual (Vn side only)
static __device__ __half  g_pthi[B_ * D_ * N_];     // [b][e][m]  P transposed, fp16

// ---------------- PTX helpers (baseline ISA only: sm_80-level) ----------------
__device__ __forceinline__ unsigned smem_u32(const void* p) {
    unsigned a;
    asm("{ .reg .u64 t; cvta.to.shared.u64 t, %1; cvt.u32.u64 %0, t; }" : "=r"(a) : "l"(p));
    return a;
}
__device__ __forceinline__ void cpa16(unsigned dst, const void* src) {
    asm volatile("cp.async.cg.shared.global [%0], [%1], 16;" :: "r"(dst), "l"(src) : "memory");
}
#define CP_COMMIT() asm volatile("cp.async.commit_group;" ::: "memory")
#define CP_WAIT0()  asm volatile("cp.async.wait_group 0;" ::: "memory")
#define CP_WAIT1()  asm volatile("cp.async.wait_group 1;" ::: "memory")

__device__ __forceinline__ void ldm4(unsigned* r, unsigned addr) {
    asm volatile("ldmatrix.sync.aligned.m8n8.x4.shared.b16 {%0,%1,%2,%3}, [%4];"
                 : "=r"(r[0]), "=r"(r[1]), "=r"(r[2]), "=r"(r[3]) : "r"(addr));
}
__device__ __forceinline__ void mmah(float* d, const unsigned* a, unsigned b0, unsigned b1) {
    asm volatile(
        "mma.sync.aligned.m16n8k16.row.col.f32.f16.f16.f32 "
        "{%0,%1,%2,%3}, {%4,%5,%6,%7}, {%8,%9}, {%0,%1,%2,%3};"
        : "+f"(d[0]), "+f"(d[1]), "+f"(d[2]), "+f"(d[3])
        : "r"(a[0]), "r"(a[1]), "r"(a[2]), "r"(a[3]), "r"(b0), "r"(b1));
}
__device__ __forceinline__ void sts32(unsigned addr, unsigned v) {
    asm volatile("st.shared.u32 [%0], %1;" :: "r"(addr), "r"(v) : "memory");
}
__device__ __forceinline__ unsigned pack_h2(float x, float y) {
    __half2 h; h.x = __float2half_rn(x); h.y = __float2half_rn(y);
    return *(unsigned*)&h;
}

// ---------------- prologue ----------------
__device__ __forceinline__ unsigned long long ffma2(unsigned long long a,
                                                    unsigned long long b,
                                                    unsigned long long c) {
    unsigned long long d;
    asm("fma.rn.f32x2 %0, %1, %2, %3;" : "=l"(d) : "l"(a), "l"(b), "l"(c));
    return d;
}
__device__ __forceinline__ unsigned long long dup2(float x) {
    unsigned long long d;
    asm("mov.b64 %0, {%1, %1};" : "=l"(d) : "f"(x));
    return d;
}
union V4 { float4 f; unsigned long long u[2]; };

// proj + transpose + fp16 convert fused: writes g_pthi[b][e][m] directly
__global__ __launch_bounds__(256, 2)
void proj_kernel(const float* __restrict__ val, const float* __restrict__ Wv) {
    __shared__ float As[64 * 36];
    __shared__ float Bs[32 * 68];
    __shared__ float Ts[64 * 65];
    const int t = threadIdx.x;
    const int tx = t & 15, ty = t >> 4;
    const int row0 = blockIdx.y * 64;
    const int e0 = blockIdx.x * 64;
    unsigned long long acc[4][2] = {};
    for (int k0 = 0; k0 < D_; k0 += 32) {
#pragma unroll
        for (int p = 0; p < 2; p++) {
            int idx = p * 256 + t, r = idx >> 3, q = idx & 7;
            *(float4*)&As[r * 36 + q * 4] =
                *(const float4*)&val[(size_t)(row0 + r) * D_ + k0 + q * 4];
        }
#pragma unroll
        for (int p = 0; p < 2; p++) {
            int idx = p * 256 + t, kr = idx >> 4, ec = idx & 15;
            *(float4*)&Bs[kr * 68 + ec * 4] =
                *(const float4*)&Wv[(k0 + kr) * D_ + e0 + ec * 4];
        }
        __syncthreads();
#pragma unroll 16
        for (int kk = 0; kk < 32; kk++) {
            V4 bv; bv.f = *(float4*)&Bs[kk * 68 + tx * 4];
#pragma unroll
            for (int i = 0; i < 4; i++) {
                unsigned long long a2 = dup2(As[(ty * 4 + i) * 36 + kk]);
                acc[i][0] = ffma2(a2, bv.u[0], acc[i][0]);
                acc[i][1] = ffma2(a2, bv.u[1], acc[i][1]);
            }
        }
        __syncthreads();
    }
#pragma unroll
    for (int i = 0; i < 4; i++) {
        V4 o; o.u[0] = acc[i][0]; o.u[1] = acc[i][1];
        float v4[4] = {o.f.x, o.f.y, o.f.z, o.f.w};
#pragma unroll
        for (int q = 0; q < 4; q++)
            Ts[(tx * 4 + q) * 65 + ty * 4 + i] = v4[q];
    }
    __syncthreads();
    {
        const int b = row0 >> 12, m0l = row0 & (N_ - 1);
        const int e_l = t >> 2, ms = (t & 3) * 16;
        unsigned hw[8];
#pragma unroll
        for (int jj = 0; jj < 8; jj++)
            hw[jj] = pack_h2(Ts[e_l * 65 + ms + 2 * jj], Ts[e_l * 65 + ms + 2 * jj + 1]);
        size_t o = ((size_t)(b * D_ + e0 + e_l)) * N_ + m0l + ms;
        *(uint4*)(g_pthi + o)     = make_uint4(hw[0], hw[1], hw[2], hw[3]);
        *(uint4*)(g_pthi + o + 8) = make_uint4(hw[4], hw[5], hw[6], hw[7]);
    }
}

__global__ __launch_bounds__(256)
void split_val(const float* __restrict__ val) {
    size_t i = ((size_t)blockIdx.x * 256 + threadIdx.x) * 4;
    float4 v = *(const float4*)(val + i);
    float a[4] = {v.x, v.y, v.z, v.w};
#pragma unroll
    for (int k = 0; k < 4; k += 2) {
        __half h0 = __float2half_rn(a[k]);
        __half h1 = __float2half_rn(a[k + 1]);
        __half2 hp; hp.x = h0; hp.y = h1;
        __half2 lp;
        lp.x = __float2half_rn(a[k] - __half2float(h0));
        lp.y = __float2half_rn(a[k + 1] - __half2float(h1));
        *(__half2*)(g_vhi + i + k) = hp;
        *(__half2*)(g_vlo + i + k) = lp;
    }
}

// ---------------- main fused kernel ----------------
// SMEM layout (bytes)
#define OFF_VNH 0u         // Vn_hi 128 rows x 512B (swizzled)   65536
#define OFF_VNL 65536u     // Vn_lo                               65536
#define OFF_VM  131072u    // Vm_hi double buffer: 2 x 16K        32768
#define OFF_PT  163840u    // Pt_hi 256 rows x 80B                20480
#define OFF_EH  184320u    // E_hi 128 rows x 80B                 10240
#define OFF_DS  194560u    // 128 floats
#define SMEM_SZ 195072u

__global__ __launch_bounds__(512, 1)
void prop_mma(const float* __restrict__ state, float* __restrict__ out) {
    extern __shared__ __align__(128) char sm[];
    const unsigned sb = smem_u32(sm);
    const int t = threadIdx.x;
    const int lane = t & 31, w = t >> 5;
    // Phase A layout: 8 rg (m16) x 2 ch (n16)
    const int rg = w >> 1, ch = w & 1;
    const int RG = rg * 16;
    // Phase B layout: 4 rg2 (m32) x 4 ch2 (e64)
    const int rg2 = w >> 2, ch2 = w & 3;
    const int RG2 = rg2 * 32;
    const int b = blockIdx.y;
    const int n0 = blockIdx.x * 128;

    const __half* vh  = g_vhi  + (size_t)b * N_ * D_;
    const __half* vl  = g_vlo  + (size_t)b * N_ * D_;
    const __half* pth = g_pthi + (size_t)b * D_ * N_;
    const float* stb = state + b * N_;

    float* ds_sm = (float*)(sm + OFF_DS);
    if (t < 128) ds_sm[t] = 0.f;

    // ---- prologue loads: Vn (persistent) + Vm[0] into buf0 : one commit group ----
#pragma unroll
    for (int j = 0; j < 8; j++) {
        int idx = j * 512 + t, row = idx >> 5, kc = idx & 31;
        unsigned swz = (unsigned)(row * 512) + (((unsigned)kc * 16) ^ (((unsigned)row & 7) << 4));
        cpa16(sb + OFF_VNH + swz, vh + (size_t)(n0 + row) * D_ + kc * 8);
        cpa16(sb + OFF_VNL + swz, vl + (size_t)(n0 + row) * D_ + kc * 8);
    }
    {
        int row = t >> 4, kc2 = t & 15;   // 512 thr: 32 rows x 16 of 32 kc
#pragma unroll
        for (int j = 0; j < 2; j++) {
            int kc = kc2 * 2 + j;
            unsigned swz = (unsigned)(row * 512) + (((unsigned)kc * 16) ^ (((unsigned)row & 7) << 4));
            cpa16(sb + OFF_VM + swz, vh + (size_t)row * D_ + kc * 8);
        }
    }
    CP_COMMIT();

    float accD[64];
#pragma unroll
    for (int q = 0; q < 64; q++) accD[q] = 0.f;
    float ds0 = 0.f, ds1 = 0.f;

    // Phase A fragment addresses
    const unsigned aRow = RG + (lane & 15);
    const unsigned aK   = ((unsigned)lane >> 4) * 16;
    const unsigned aSw  = (aRow & 7) << 4;
    const unsigned aBase = aRow * 512;
    const unsigned bRow = (unsigned)(ch * 16) + (((unsigned)lane >> 4) << 3) + (lane & 7);
    const unsigned bK   = (((unsigned)lane >> 3) & 1) * 16;
    const unsigned bSw  = (bRow & 7) << 4;
    const unsigned bBase = bRow * 512;
    // Phase B fragment addresses
    const unsigned eB0 = (unsigned)(RG2 + (lane & 15)) * 80 + ((unsigned)lane >> 4) * 16;
    const unsigned eB1 = eB0 + 16 * 80;
    const unsigned pB  = ((unsigned)(ch2 * 64) + (((unsigned)lane >> 4) << 3) + (lane & 7)) * 80
                       + (((unsigned)lane >> 3) & 1) * 16;
    const int r = lane >> 2, c = (lane & 3) * 2;
    const int Cb0 = ch * 16 + c;

#pragma unroll 1
    for (int i = 0; i < NITER; i++) {
        const int m0 = i * MC;
        CP_WAIT0();            // Vm[i] (own groups) complete
        __syncthreads();       // b1: Vm[i] visible; Phase B(i-1) done -> E, Pt free

        // issue Vm[i+1] (hi only) into the other buffer (clamped on last iter)
        const int m1 = (i < NITER - 1) ? m0 + MC : 0;
        {
            unsigned nb = sb + OFF_VM + (unsigned)((i + 1) & 1) * 16384u;
            int row = t >> 4, kc2 = t & 15;
#pragma unroll
            for (int j = 0; j < 2; j++) {
                int kc = kc2 * 2 + j;
                unsigned swz = (unsigned)(row * 512) + (((unsigned)kc * 16) ^ (((unsigned)row & 7) << 4));
                cpa16(nb + swz, vh + (size_t)(m1 + row) * D_ + kc * 8);
            }
            CP_COMMIT();
        }
        // issue Pt[i]  (single buffer; safe: Phase B(i-1) done at b1)
#pragma unroll
        for (int j = 0; j < 2; j++) {
            int idx = j * 512 + t, row = idx >> 2, kc = idx & 3;
            unsigned o = (unsigned)(row * 80 + kc * 16);
            cpa16(sb + OFF_PT + o, pth + (size_t)row * N_ + m0 + kc * 8);
        }
        CP_COMMIT();

        // early state loads (latency hides under Phase A)
        float sc[4];
        sc[0] = __ldg(stb + m0 + Cb0);
        sc[1] = __ldg(stb + m0 + Cb0 + 1);
        sc[2] = __ldg(stb + m0 + Cb0 + 8);
        sc[3] = __ldg(stb + m0 + Cb0 + 9);

        // -------- Phase A: S[128x32] = Vn . Vm^T, fp16 2-term (hh + lh) --------
        const unsigned vmb = sb + OFF_VM + (unsigned)(i & 1) * 16384u;
        float accS[8];
#pragma unroll
        for (int q = 0; q < 8; q++) accS[q] = 0.f;
#pragma unroll
        for (int ks = 0; ks < 16; ks++) {
            unsigned ah[4], al[4], bh[4];
            unsigned ka = ((unsigned)(ks * 32) + aK) ^ aSw;
            ldm4(ah, sb + OFF_VNH + aBase + ka);
            ldm4(al, sb + OFF_VNL + aBase + ka);
            unsigned kb = ((unsigned)(ks * 32) + bK) ^ bSw;
            ldm4(bh, vmb + bBase + kb);
            mmah(accS,     ah, bh[0], bh[1]);
            mmah(accS + 4, ah, bh[2], bh[3]);
            mmah(accS,     al, bh[0], bh[1]);
            mmah(accS + 4, al, bh[2], bh[3]);
        }

        // -------- epilogue: softsign, delta_state, E (fp16) -> SMEM --------
#pragma unroll
        for (int tl = 0; tl < 2; tl++) {
            int Cb = Cb0 + tl * 8;
            float s0 = accS[tl * 4 + 0], s1 = accS[tl * 4 + 1];
            float s2 = accS[tl * 4 + 2], s3 = accS[tl * 4 + 3];
            float e0 = __fdividef(s0, 1.f + fabsf(s0));
            float e1 = __fdividef(s1, 1.f + fabsf(s1));
            float e2 = __fdividef(s2, 1.f + fabsf(s2));
            float e3 = __fdividef(s3, 1.f + fabsf(s3));
            ds0 += e0 * sc[tl * 2] + e1 * sc[tl * 2 + 1];
            ds1 += e2 * sc[tl * 2] + e3 * sc[tl * 2 + 1];
            unsigned o0 = (unsigned)((RG + r) * 80 + Cb * 2);
            sts32(sb + OFF_EH + o0, pack_h2(e0, e1));
            sts32(sb + OFF_EH + o0 + 8 * 80, pack_h2(e2, e3));
        }
        CP_WAIT1();            // Pt[i] done (Vm[i+1] still in flight)
        __syncthreads();       // b2: E + Pt visible

        // -------- Phase B: dval[128x256] += E . Pt^T, fp16 1-term --------
#pragma unroll
        for (int ks = 0; ks < 2; ks++) {
            unsigned eh0[4], eh1[4];
            ldm4(eh0, sb + OFF_EH + eB0 + ks * 32);
            ldm4(eh1, sb + OFF_EH + eB1 + ks * 32);
#pragma unroll
            for (int g = 0; g < 4; g++) {
                unsigned ph[4];
                unsigned po = pB + (unsigned)(g * 16 * 80 + ks * 32);
                ldm4(ph, sb + OFF_PT + po);
                float* d00 = accD + ((0 * 4 + g) * 2 + 0) * 4;
                float* d01 = accD + ((0 * 4 + g) * 2 + 1) * 4;
                float* d10 = accD + ((1 * 4 + g) * 2 + 0) * 4;
                float* d11 = accD + ((1 * 4 + g) * 2 + 1) * 4;
                mmah(d00, eh0, ph[0], ph[1]);
                mmah(d10, eh1, ph[0], ph[1]);
                mmah(d01, eh0, ph[2], ph[3]);
                mmah(d11, eh1, ph[2], ph[3]);
            }
        }
    }

    // -------- write delta_val (Phase B layout) --------
    float* dvb = out + B_ * N_ + ((size_t)(b * N_ + n0)) * D_;
#pragma unroll
    for (int s = 0; s < 2; s++) {
#pragma unroll
        for (int g = 0; g < 4; g++) {
#pragma unroll
            for (int h2 = 0; h2 < 2; h2++) {
                int row = RG2 + s * 16 + r;
                int col = ch2 * 64 + g * 16 + h2 * 8 + c;
                const float* d = accD + ((s * 4 + g) * 2 + h2) * 4;
                float2 lo; lo.x = d[0]; lo.y = d[1];
                float2 hi; hi.x = d[2]; hi.y = d[3];
                *(float2*)(dvb + (size_t)row * D_ + col) = lo;
                *(float2*)(dvb + (size_t)(row + 8) * D_ + col) = hi;
            }
        }
    }

    // -------- reduce & write delta_state (Phase A layout) --------
    ds0 += __shfl_xor_sync(0xffffffffu, ds0, 1);
    ds0 += __shfl_xor_sync(0xffffffffu, ds0, 2);
    ds1 += __shfl_xor_sync(0xffffffffu, ds1, 1);
    ds1 += __shfl_xor_sync(0xffffffffu, ds1, 2);
    if ((lane & 3) == 0) {
        atomicAdd(ds_sm + RG + r, ds0);
        atomicAdd(ds_sm + RG + r + 8, ds1);
    }
    __syncthreads();
    if (t < 128) out[b * N_ + n0 + t] = ds_sm[t];
}

extern "C" void kernel_launch(void* const* d_in, const int* in_sizes, int n_in,
                              void* d_out, int out_size) {
    const float* val   = (const float*)d_in[0];  // [B, N, D]
    const float* state = (const float*)d_in[1];  // [B, N]
    const float* Wv    = (const float*)d_in[2];  // [D, D]
    float* out = (float*)d_out;                  // [B*N] delta_state, [B*N*D] delta_val
    (void)in_sizes; (void)n_in; (void)out_size;

    cudaFuncSetAttribute(prop_mma, cudaFuncAttributeMaxDynamicSharedMemorySize, SMEM_SZ);

    split_val<<<(B_ * N_ * D_) / 1024, 256>>>(val);
    proj_kernel<<<dim3(D_ / 64, (B_ * N_) / 64), 256>>>(val, Wv);
    prop_mma<<<dim3(N_ / 128, B_), 512, SMEM_SZ>>>(state, out);
}

// round 12
// speedup vs baseline: 1.7286x; 1.0159x over previous
#include <cuda_runtime.h>
#include <cuda_fp16.h>

#define B_ 4
#define N_ 4096
#define D_ 256
#define MC 32                 // m-chunk
#define NITER (N_ / MC)       // 128

// Device-global scratch (allocation-free rule)
static __device__ __half  g_vhi[B_ * N_ * D_];      // [b][n][d] fp16 hi
static __device__ __half  g_vlo[B_ * N_ * D_];      // fp16 lo residual (Vn side only)
static __device__ __half  g_pthi[B_ * D_ * N_];     // [b][e][m]  P transposed, fp16

// ---------------- PTX helpers (baseline ISA only: sm_80-level) ----------------
__device__ __forceinline__ unsigned smem_u32(const void* p) {
    unsigned a;
    asm("{ .reg .u64 t; cvta.to.shared.u64 t, %1; cvt.u32.u64 %0, t; }" : "=r"(a) : "l"(p));
    return a;
}
__device__ __forceinline__ void cpa16(unsigned dst, const void* src) {
    asm volatile("cp.async.cg.shared.global [%0], [%1], 16;" :: "r"(dst), "l"(src) : "memory");
}
#define CP_COMMIT() asm volatile("cp.async.commit_group;" ::: "memory")
#define CP_WAIT0()  asm volatile("cp.async.wait_group 0;" ::: "memory")

__device__ __forceinline__ void ldm4(unsigned* r, unsigned addr) {
    asm volatile("ldmatrix.sync.aligned.m8n8.x4.shared.b16 {%0,%1,%2,%3}, [%4];"
                 : "=r"(r[0]), "=r"(r[1]), "=r"(r[2]), "=r"(r[3]) : "r"(addr));
}
__device__ __forceinline__ void mmah(float* d, const unsigned* a, unsigned b0, unsigned b1) {
    asm volatile(
        "mma.sync.aligned.m16n8k16.row.col.f32.f16.f16.f32 "
        "{%0,%1,%2,%3}, {%4,%5,%6,%7}, {%8,%9}, {%0,%1,%2,%3};"
        : "+f"(d[0]), "+f"(d[1]), "+f"(d[2]), "+f"(d[3])
        : "r"(a[0]), "r"(a[1]), "r"(a[2]), "r"(a[3]), "r"(b0), "r"(b1));
}
__device__ __forceinline__ void sts32(unsigned addr, unsigned v) {
    asm volatile("st.shared.u32 [%0], %1;" :: "r"(addr), "r"(v) : "memory");
}
__device__ __forceinline__ unsigned pack_h2(float x, float y) {
    __half2 h; h.x = __float2half_rn(x); h.y = __float2half_rn(y);
    return *(unsigned*)&h;
}

// ---------------- prologue ----------------
__device__ __forceinline__ unsigned long long ffma2(unsigned long long a,
                                                    unsigned long long b,
                                                    unsigned long long c) {
    unsigned long long d;
    asm("fma.rn.f32x2 %0, %1, %2, %3;" : "=l"(d) : "l"(a), "l"(b), "l"(c));
    return d;
}
__device__ __forceinline__ unsigned long long dup2(float x) {
    unsigned long long d;
    asm("mov.b64 %0, {%1, %1};" : "=l"(d) : "f"(x));
    return d;
}
union V4 { float4 f; unsigned long long u[2]; };

// proj + transpose + fp16 convert fused: writes g_pthi[b][e][m] directly
__global__ __launch_bounds__(256, 2)
void proj_kernel(const float* __restrict__ val, const float* __restrict__ Wv) {
    __shared__ float As[64 * 36];
    __shared__ float Bs[32 * 68];
    __shared__ float Ts[64 * 65];
    const int t = threadIdx.x;
    const int tx = t & 15, ty = t >> 4;
    const int row0 = blockIdx.y * 64;
    const int e0 = blockIdx.x * 64;
    unsigned long long acc[4][2] = {};
    for (int k0 = 0; k0 < D_; k0 += 32) {
#pragma unroll
        for (int p = 0; p < 2; p++) {
            int idx = p * 256 + t, r = idx >> 3, q = idx & 7;
            *(float4*)&As[r * 36 + q * 4] =
                *(const float4*)&val[(size_t)(row0 + r) * D_ + k0 + q * 4];
        }
#pragma unroll
        for (int p = 0; p < 2; p++) {
            int idx = p * 256 + t, kr = idx >> 4, ec = idx & 15;
            *(float4*)&Bs[kr * 68 + ec * 4] =
                *(const float4*)&Wv[(k0 + kr) * D_ + e0 + ec * 4];
        }
        __syncthreads();
#pragma unroll 16
        for (int kk = 0; kk < 32; kk++) {
            V4 bv; bv.f = *(float4*)&Bs[kk * 68 + tx * 4];
#pragma unroll
            for (int i = 0; i < 4; i++) {
                unsigned long long a2 = dup2(As[(ty * 4 + i) * 36 + kk]);
                acc[i][0] = ffma2(a2, bv.u[0], acc[i][0]);
                acc[i][1] = ffma2(a2, bv.u[1], acc[i][1]);
            }
        }
        __syncthreads();
    }
#pragma unroll
    for (int i = 0; i < 4; i++) {
        V4 o; o.u[0] = acc[i][0]; o.u[1] = acc[i][1];
        float v4[4] = {o.f.x, o.f.y, o.f.z, o.f.w};
#pragma unroll
        for (int q = 0; q < 4; q++)
            Ts[(tx * 4 + q) * 65 + ty * 4 + i] = v4[q];
    }
    __syncthreads();
    {
        const int b = row0 >> 12, m0l = row0 & (N_ - 1);
        const int e_l = t >> 2, ms = (t & 3) * 16;
        unsigned hw[8];
#pragma unroll
        for (int jj = 0; jj < 8; jj++)
            hw[jj] = pack_h2(Ts[e_l * 65 + ms + 2 * jj], Ts[e_l * 65 + ms + 2 * jj + 1]);
        size_t o = ((size_t)(b * D_ + e0 + e_l)) * N_ + m0l + ms;
        *(uint4*)(g_pthi + o)     = make_uint4(hw[0], hw[1], hw[2], hw[3]);
        *(uint4*)(g_pthi + o + 8) = make_uint4(hw[4], hw[5], hw[6], hw[7]);
    }
}

__global__ __launch_bounds__(256)
void split_val(const float* __restrict__ val) {
    size_t i = ((size_t)blockIdx.x * 256 + threadIdx.x) * 4;
    float4 v = *(const float4*)(val + i);
    float a[4] = {v.x, v.y, v.z, v.w};
#pragma unroll
    for (int k = 0; k < 4; k += 2) {
        __half h0 = __float2half_rn(a[k]);
        __half h1 = __float2half_rn(a[k + 1]);
        __half2 hp; hp.x = h0; hp.y = h1;
        __half2 lp;
        lp.x = __float2half_rn(a[k] - __half2float(h0));
        lp.y = __float2half_rn(a[k + 1] - __half2float(h1));
        *(__half2*)(g_vhi + i + k) = hp;
        *(__half2*)(g_vlo + i + k) = lp;
    }
}

// ---------------- main fused kernel ----------------
// SMEM layout (bytes)
#define OFF_VNH 0u         // Vn_hi 128 rows x 512B (swizzled)   65536
#define OFF_VNL 65536u     // Vn_lo                               65536
#define OFF_VM  131072u    // Vm_hi double buffer: 2 x 16K        32768
#define OFF_PT  163840u    // Pt double buffer: 2 x 20480         40960
#define OFF_EH  204800u    // E double buffer: 2 x 10240          20480
#define OFF_DS  225280u    // 128 floats
#define SMEM_SZ 225792u

__global__ __launch_bounds__(512, 1)
void prop_mma(const float* __restrict__ state, float* __restrict__ out) {
    extern __shared__ __align__(128) char sm[];
    const unsigned sb = smem_u32(sm);
    const int t = threadIdx.x;
    const int lane = t & 31, w = t >> 5;
    // Phase A layout: 8 rg (m16) x 2 ch (n16)
    const int rg = w >> 1, ch = w & 1;
    const int RG = rg * 16;
    // Phase B layout: 4 rg2 (m32) x 4 ch2 (e64)
    const int rg2 = w >> 2, ch2 = w & 3;
    const int RG2 = rg2 * 32;
    const int b = blockIdx.y;
    const int n0 = blockIdx.x * 128;

    const __half* vh  = g_vhi  + (size_t)b * N_ * D_;
    const __half* vl  = g_vlo  + (size_t)b * N_ * D_;
    const __half* pth = g_pthi + (size_t)b * D_ * N_;
    const float* stb = state + b * N_;

    float* ds_sm = (float*)(sm + OFF_DS);
    if (t < 128) ds_sm[t] = 0.f;

    // ---- prologue loads: Vn (persistent) + Vm[0] into buf0 : one commit group ----
#pragma unroll
    for (int j = 0; j < 8; j++) {
        int idx = j * 512 + t, row = idx >> 5, kc = idx & 31;
        unsigned swz = (unsigned)(row * 512) + (((unsigned)kc * 16) ^ (((unsigned)row & 7) << 4));
        cpa16(sb + OFF_VNH + swz, vh + (size_t)(n0 + row) * D_ + kc * 8);
        cpa16(sb + OFF_VNL + swz, vl + (size_t)(n0 + row) * D_ + kc * 8);
    }
    {
        int row = t >> 4, kc2 = t & 15;   // 512 thr: 32 rows x 16 of 32 kc
#pragma unroll
        for (int j = 0; j < 2; j++) {
            int kc = kc2 * 2 + j;
            unsigned swz = (unsigned)(row * 512) + (((unsigned)kc * 16) ^ (((unsigned)row & 7) << 4));
            cpa16(sb + OFF_VM + swz, vh + (size_t)row * D_ + kc * 8);
        }
    }
    CP_COMMIT();

    float accD[64];
#pragma unroll
    for (int q = 0; q < 64; q++) accD[q] = 0.f;
    float ds0 = 0.f, ds1 = 0.f;

    // Phase A fragment addresses
    const unsigned aRow = RG + (lane & 15);
    const unsigned aK   = ((unsigned)lane >> 4) * 16;
    const unsigned aSw  = (aRow & 7) << 4;
    const unsigned aBase = aRow * 512;
    const unsigned bRow = (unsigned)(ch * 16) + (((unsigned)lane >> 4) << 3) + (lane & 7);
    const unsigned bK   = (((unsigned)lane >> 3) & 1) * 16;
    const unsigned bSw  = (bRow & 7) << 4;
    const unsigned bBase = bRow * 512;
    // Phase B fragment addresses (within one E/Pt buffer)
    const unsigned eB0 = (unsigned)(RG2 + (lane & 15)) * 80 + ((unsigned)lane >> 4) * 16;
    const unsigned eB1 = eB0 + 16 * 80;
    const unsigned pB  = ((unsigned)(ch2 * 64) + (((unsigned)lane >> 4) << 3) + (lane & 7)) * 80
                       + (((unsigned)lane >> 3) & 1) * 16;
    const int r = lane >> 2, c = (lane & 3) * 2;
    const int Cb0 = ch * 16 + c;

#pragma unroll 1
    for (int i = 0; i < NITER; i++) {
        const int m0 = i * MC;
        CP_WAIT0();            // Vm[i] (+ Pt[i-1]) complete
        __syncthreads();       // SINGLE barrier: Vm[i], Pt[i-1], E[i-1] visible;
                               // ring buffers written this iter were fully read in iter i-1

        // issue Vm[i+1] (hi only) into buf (i+1)&1  (clamped on last iter)
        const int m1 = (i < NITER - 1) ? m0 + MC : 0;
        {
            unsigned nb = sb + OFF_VM + (unsigned)((i + 1) & 1) * 16384u;
            int row = t >> 4, kc2 = t & 15;
#pragma unroll
            for (int j = 0; j < 2; j++) {
                int kc = kc2 * 2 + j;
                unsigned swz = (unsigned)(row * 512) + (((unsigned)kc * 16) ^ (((unsigned)row & 7) << 4));
                cpa16(nb + swz, vh + (size_t)(m1 + row) * D_ + kc * 8);
            }
            CP_COMMIT();
        }
        // issue Pt[i] into buf i&1 (read next iter by Phase B(i))
        {
            unsigned pdst = sb + OFF_PT + (unsigned)(i & 1) * 20480u;
#pragma unroll
            for (int j = 0; j < 2; j++) {
                int idx = j * 512 + t, row = idx >> 2, kc = idx & 3;
                unsigned o = (unsigned)(row * 80 + kc * 16);
                cpa16(pdst + o, pth + (size_t)row * N_ + m0 + kc * 8);
            }
            CP_COMMIT();
        }

        // early state loads (latency hides under Phase B/A)
        float sc[4];
        sc[0] = __ldg(stb + m0 + Cb0);
        sc[1] = __ldg(stb + m0 + Cb0 + 1);
        sc[2] = __ldg(stb + m0 + Cb0 + 8);
        sc[3] = __ldg(stb + m0 + Cb0 + 9);

        // -------- Phase B(i-1): dval += E(i-1) . Pt(i-1)^T, fp16 1-term --------
        if (i > 0) {
            const unsigned ebuf = sb + OFF_EH + (unsigned)((i - 1) & 1) * 10240u;
            const unsigned pbuf = sb + OFF_PT + (unsigned)((i - 1) & 1) * 20480u;
#pragma unroll
            for (int ks = 0; ks < 2; ks++) {
                unsigned eh0[4], eh1[4];
                ldm4(eh0, ebuf + eB0 + ks * 32);
                ldm4(eh1, ebuf + eB1 + ks * 32);
#pragma unroll
                for (int g = 0; g < 4; g++) {
                    unsigned ph[4];
                    unsigned po = pB + (unsigned)(g * 16 * 80 + ks * 32);
                    ldm4(ph, pbuf + po);
                    float* d00 = accD + ((0 * 4 + g) * 2 + 0) * 4;
                    float* d01 = accD + ((0 * 4 + g) * 2 + 1) * 4;
                    float* d10 = accD + ((1 * 4 + g) * 2 + 0) * 4;
                    float* d11 = accD + ((1 * 4 + g) * 2 + 1) * 4;
                    mmah(d00, eh0, ph[0], ph[1]);
                    mmah(d10, eh1, ph[0], ph[1]);
                    mmah(d01, eh0, ph[2], ph[3]);
                    mmah(d11, eh1, ph[2], ph[3]);
                }
            }
        }

        // -------- Phase A(i): S[128x32] = Vn . Vm^T, fp16 2-term (hh + lh) --------
        const unsigned vmb = sb + OFF_VM + (unsigned)(i & 1) * 16384u;
        float accS[8];
#pragma unroll
        for (int q = 0; q < 8; q++) accS[q] = 0.f;
#pragma unroll
        for (int ks = 0; ks < 16; ks++) {
            unsigned ah[4], al[4], bh[4];
            unsigned ka = ((unsigned)(ks * 32) + aK) ^ aSw;
            ldm4(ah, sb + OFF_VNH + aBase + ka);
            ldm4(al, sb + OFF_VNL + aBase + ka);
            unsigned kb = ((unsigned)(ks * 32) + bK) ^ bSw;
            ldm4(bh, vmb + bBase + kb);
            mmah(accS,     ah, bh[0], bh[1]);
            mmah(accS + 4, ah, bh[2], bh[3]);
            mmah(accS,     al, bh[0], bh[1]);
            mmah(accS + 4, al, bh[2], bh[3]);
        }

        // -------- epilogue(i): softsign, delta_state, E(i) -> buf i&1 --------
        {
            const unsigned edst = sb + OFF_EH + (unsigned)(i & 1) * 10240u;
#pragma unroll
            for (int tl = 0; tl < 2; tl++) {
                int Cb = Cb0 + tl * 8;
                float s0 = accS[tl * 4 + 0], s1 = accS[tl * 4 + 1];
                float s2 = accS[tl * 4 + 2], s3 = accS[tl * 4 + 3];
                float e0 = __fdividef(s0, 1.f + fabsf(s0));
                float e1 = __fdividef(s1, 1.f + fabsf(s1));
                float e2 = __fdividef(s2, 1.f + fabsf(s2));
                float e3 = __fdividef(s3, 1.f + fabsf(s3));
                ds0 += e0 * sc[tl * 2] + e1 * sc[tl * 2 + 1];
                ds1 += e2 * sc[tl * 2] + e3 * sc[tl * 2 + 1];
                unsigned o0 = (unsigned)((RG + r) * 80 + Cb * 2);
                sts32(edst + o0, pack_h2(e0, e1));
                sts32(edst + o0 + 8 * 80, pack_h2(e2, e3));
            }
        }
    }

    // -------- peeled Phase B(NITER-1) --------
    CP_WAIT0();
    __syncthreads();
    {
        const unsigned ebuf = sb + OFF_EH + (unsigned)((NITER - 1) & 1) * 10240u;
        const unsigned pbuf = sb + OFF_PT + (unsigned)((NITER - 1) & 1) * 20480u;
#pragma unroll
        for (int ks = 0; ks < 2; ks++) {
            unsigned eh0[4], eh1[4];
            ldm4(eh0, ebuf + eB0 + ks * 32);
            ldm4(eh1, ebuf + eB1 + ks * 32);
#pragma unroll
            for (int g = 0; g < 4; g++) {
                unsigned ph[4];
                unsigned po = pB + (unsigned)(g * 16 * 80 + ks * 32);
                ldm4(ph, pbuf + po);
                float* d00 = accD + ((0 * 4 + g) * 2 + 0) * 4;
                float* d01 = accD + ((0 * 4 + g) * 2 + 1) * 4;
                float* d10 = accD + ((1 * 4 + g) * 2 + 0) * 4;
                float* d11 = accD + ((1 * 4 + g) * 2 + 1) * 4;
                mmah(d00, eh0, ph[0], ph[1]);
                mmah(d10, eh1, ph[0], ph[1]);
                mmah(d01, eh0, ph[2], ph[3]);
                mmah(d11, eh1, ph[2], ph[3]);
            }
        }
    }

    // -------- write delta_val (Phase B layout) --------
    float* dvb = out + B_ * N_ + ((size_t)(b * N_ + n0)) * D_;
#pragma unroll
    for (int s = 0; s < 2; s++) {
#pragma unroll
        for (int g = 0; g < 4; g++) {
#pragma unroll
            for (int h2 = 0; h2 < 2; h2++) {
                int row = RG2 + s * 16 + r;
                int col = ch2 * 64 + g * 16 + h2 * 8 + c;
                const float* d = accD + ((s * 4 + g) * 2 + h2) * 4;
                float2 lo; lo.x = d[0]; lo.y = d[1];
                float2 hi; hi.x = d[2]; hi.y = d[3];
                *(float2*)(dvb + (size_t)row * D_ + col) = lo;
                *(float2*)(dvb + (size_t)(row + 8) * D_ + col) = hi;
            }
        }
    }

    // -------- reduce & write delta_state (Phase A layout) --------
    ds0 += __shfl_xor_sync(0xffffffffu, ds0, 1);
    ds0 += __shfl_xor_sync(0xffffffffu, ds0, 2);
    ds1 += __shfl_xor_sync(0xffffffffu, ds1, 1);
    ds1 += __shfl_xor_sync(0xffffffffu, ds1, 2);
    if ((lane & 3) == 0) {
        atomicAdd(ds_sm + RG + r, ds0);
        atomicAdd(ds_sm + RG + r + 8, ds1);
    }
    __syncthreads();
    if (t < 128) out[b * N_ + n0 + t] = ds_sm[t];
}

extern "C" void kernel_launch(void* const* d_in, const int* in_sizes, int n_in,
                              void* d_out, int out_size) {
    const float* val   = (const float*)d_in[0];  // [B, N, D]
    const float* state = (const float*)d_in[1];  // [B, N]
    const float* Wv    = (const float*)d_in[2];  // [D, D]
    float* out = (float*)d_out;                  // [B*N] delta_state, [B*N*D] delta_val
    (void)in_sizes; (void)n_in; (void)out_size;

    cudaFuncSetAttribute(prop_mma, cudaFuncAttributeMaxDynamicSharedMemorySize, SMEM_SZ);

    split_val<<<(B_ * N_ * D_) / 1024, 256>>>(val);
    proj_kernel<<<dim3(D_ / 64, (B_ * N_) / 64), 256>>>(val, Wv);
    prop_mma<<<dim3(N_ / 128, B_), 512, SMEM_SZ>>>(state, out);
}

// round 14
// speedup vs baseline: 1.8706x; 1.0821x over previous
#include <cuda_runtime.h>
#include <cuda_fp16.h>

#define B_ 4
#define N_ 4096
#define D_ 256

// Device-global scratch (allocation-free rule)
static __device__ __half  g_vhi[B_ * N_ * D_];      // [b][n][d] fp16 hi
static __device__ __half  g_vlo[B_ * N_ * D_];      // fp16 lo residual
static __device__ __half  g_pthi[B_ * D_ * N_];     // [b][e][m]  P transposed, fp16
static __device__ __half  g_E[(size_t)B_ * N_ * N_];// [b][n][m]  edges, fp16 (134MB)

// ---------------- PTX helpers ----------------
__device__ __forceinline__ unsigned smem_u32(const void* p) {
    unsigned a;
    asm("{ .reg .u64 t; cvta.to.shared.u64 t, %1; cvt.u32.u64 %0, t; }" : "=r"(a) : "l"(p));
    return a;
}
__device__ __forceinline__ void cpa16(unsigned dst, const void* src) {
    asm volatile("cp.async.cg.shared.global [%0], [%1], 16;" :: "r"(dst), "l"(src) : "memory");
}
#define CP_COMMIT() asm volatile("cp.async.commit_group;" ::: "memory")
#define CP_WAIT0()  asm volatile("cp.async.wait_group 0;" ::: "memory")

__device__ __forceinline__ void ldm4(unsigned* r, unsigned addr) {
    asm volatile("ldmatrix.sync.aligned.m8n8.x4.shared.b16 {%0,%1,%2,%3}, [%4];"
                 : "=r"(r[0]), "=r"(r[1]), "=r"(r[2]), "=r"(r[3]) : "r"(addr));
}
__device__ __forceinline__ void mmah(float* d, const unsigned* a, unsigned b0, unsigned b1) {
    asm volatile(
        "mma.sync.aligned.m16n8k16.row.col.f32.f16.f16.f32 "
        "{%0,%1,%2,%3}, {%4,%5,%6,%7}, {%8,%9}, {%0,%1,%2,%3};"
        : "+f"(d[0]), "+f"(d[1]), "+f"(d[2]), "+f"(d[3])
        : "r"(a[0]), "r"(a[1]), "r"(a[2]), "r"(a[3]), "r"(b0), "r"(b1));
}
__device__ __forceinline__ void sts32(unsigned addr, unsigned v) {
    asm volatile("st.shared.u32 [%0], %1;" :: "r"(addr), "r"(v) : "memory");
}
__device__ __forceinline__ unsigned lds32(unsigned addr) {
    unsigned v;
    asm volatile("ld.shared.u32 %0, [%1];" : "=r"(v) : "r"(addr));
    return v;
}
__device__ __forceinline__ unsigned pack_h2(float x, float y) {
    __half2 h; h.x = __float2half_rn(x); h.y = __float2half_rn(y);
    return *(unsigned*)&h;
}
__device__ __forceinline__ float softsign(float s) {
    return __fdividef(s, 1.f + fabsf(s));
}

// ---------------- prologue ----------------
__device__ __forceinline__ unsigned long long ffma2(unsigned long long a,
                                                    unsigned long long b,
                                                    unsigned long long c) {
    unsigned long long d;
    asm("fma.rn.f32x2 %0, %1, %2, %3;" : "=l"(d) : "l"(a), "l"(b), "l"(c));
    return d;
}
__device__ __forceinline__ unsigned long long dup2(float x) {
    unsigned long long d;
    asm("mov.b64 %0, {%1, %1};" : "=l"(d) : "f"(x));
    return d;
}
union V4 { float4 f; unsigned long long u[2]; };

// proj + transpose + fp16 convert fused: writes g_pthi[b][e][m] directly
__global__ __launch_bounds__(256, 2)
void proj_kernel(const float* __restrict__ val, const float* __restrict__ Wv) {
    __shared__ float As[64 * 36];
    __shared__ float Bs[32 * 68];
    __shared__ float Ts[64 * 65];
    const int t = threadIdx.x;
    const int tx = t & 15, ty = t >> 4;
    const int row0 = blockIdx.y * 64;
    const int e0 = blockIdx.x * 64;
    unsigned long long acc[4][2] = {};
    for (int k0 = 0; k0 < D_; k0 += 32) {
#pragma unroll
        for (int p = 0; p < 2; p++) {
            int idx = p * 256 + t, r = idx >> 3, q = idx & 7;
            *(float4*)&As[r * 36 + q * 4] =
                *(const float4*)&val[(size_t)(row0 + r) * D_ + k0 + q * 4];
        }
#pragma unroll
        for (int p = 0; p < 2; p++) {
            int idx = p * 256 + t, kr = idx >> 4, ec = idx & 15;
            *(float4*)&Bs[kr * 68 + ec * 4] =
                *(const float4*)&Wv[(k0 + kr) * D_ + e0 + ec * 4];
        }
        __syncthreads();
#pragma unroll 16
        for (int kk = 0; kk < 32; kk++) {
            V4 bv; bv.f = *(float4*)&Bs[kk * 68 + tx * 4];
#pragma unroll
            for (int i = 0; i < 4; i++) {
                unsigned long long a2 = dup2(As[(ty * 4 + i) * 36 + kk]);
                acc[i][0] = ffma2(a2, bv.u[0], acc[i][0]);
                acc[i][1] = ffma2(a2, bv.u[1], acc[i][1]);
            }
        }
        __syncthreads();
    }
#pragma unroll
    for (int i = 0; i < 4; i++) {
        V4 o; o.u[0] = acc[i][0]; o.u[1] = acc[i][1];
        float v4[4] = {o.f.x, o.f.y, o.f.z, o.f.w};
#pragma unroll
        for (int q = 0; q < 4; q++)
            Ts[(tx * 4 + q) * 65 + ty * 4 + i] = v4[q];
    }
    __syncthreads();
    {
        const int b = row0 >> 12, m0l = row0 & (N_ - 1);
        const int e_l = t >> 2, ms = (t & 3) * 16;
        unsigned hw[8];
#pragma unroll
        for (int jj = 0; jj < 8; jj++)
            hw[jj] = pack_h2(Ts[e_l * 65 + ms + 2 * jj], Ts[e_l * 65 + ms + 2 * jj + 1]);
        size_t o = ((size_t)(b * D_ + e0 + e_l)) * N_ + m0l + ms;
        *(uint4*)(g_pthi + o)     = make_uint4(hw[0], hw[1], hw[2], hw[3]);
        *(uint4*)(g_pthi + o + 8) = make_uint4(hw[4], hw[5], hw[6], hw[7]);
    }
}

__global__ __launch_bounds__(256)
void split_val(const float* __restrict__ val) {
    size_t i = ((size_t)blockIdx.x * 256 + threadIdx.x) * 4;
    float4 v = *(const float4*)(val + i);
    float a[4] = {v.x, v.y, v.z, v.w};
#pragma unroll
    for (int k = 0; k < 4; k += 2) {
        __half h0 = __float2half_rn(a[k]);
        __half h1 = __float2half_rn(a[k + 1]);
        __half2 hp; hp.x = h0; hp.y = h1;
        __half2 lp;
        lp.x = __float2half_rn(a[k] - __half2float(h0));
        lp.y = __float2half_rn(a[k + 1] - __half2float(h1));
        *(__half2*)(g_vhi + i + k) = hp;
        *(__half2*)(g_vlo + i + k) = lp;
    }
}

// ================= kernel 1: scores -> E (upper triangle + mirror) =================
// grid (16 pairs, 2 j-halves, 4 batches) = 128 CTAs, 512 threads.
// CTA handles rows-blocks {p, 31-p}; per row-block bi, j-chunks of 64 cols from 128*bi.
#define SE_VIH 0u          // Vi_hi 128 x 512B swizzled
#define SE_VIL 65536u      // Vi_lo
#define SE_VJ  131072u     // Vj_hi double buffer 2 x 32768 (64 rows x 512B)
#define SE_ES  196608u     // E staging 128 x 136B
#define SE_SZ  214016u

__global__ __launch_bounds__(512, 1)
void score_kernel() {
    extern __shared__ __align__(128) char sm[];
    const unsigned sb = smem_u32(sm);
    const int t = threadIdx.x, lane = t & 31, w = t >> 5;
    const int rg = w >> 1, ch = w & 1;       // 8 rg (m16) x 2 ch (n32)
    const int RG = rg * 16;
    const int p = blockIdx.x, hh = blockIdx.y, b = blockIdx.z;
    const __half* vh = g_vhi + (size_t)b * N_ * D_;
    const __half* vl = g_vlo + (size_t)b * N_ * D_;
    __half* gE = g_E + (size_t)b * N_ * N_;

    // A-fragment addressing (Vi, 128 rows)
    const unsigned aRow = RG + (lane & 15);
    const unsigned aK   = ((unsigned)lane >> 4) * 16;
    const unsigned aSw  = (aRow & 7) << 4;
    const unsigned aBase = aRow * 512;
    // B-fragment addressing (Vj, 64 rows, two n16 subtiles per warp)
    const unsigned bR0 = (unsigned)(ch * 32) + (((unsigned)lane >> 4) << 3) + (lane & 7);
    const unsigned bR1 = bR0 + 16;
    const unsigned bK  = (((unsigned)lane >> 3) & 1) * 16;
    const int r = lane >> 2, c2 = (lane & 3) * 2;

    for (int phase = 0; phase < 2; phase++) {
        const int bi = phase ? 31 - p : p;
        const int half_cnt = 32 - bi;            // chunks per half (C = 64-2*bi, even)
        const int cBeg = hh * half_cnt;
        const int cEnd = cBeg + half_cnt;
        const int base = 128 * bi;

        __syncthreads();   // previous phase fully done before overwriting Vi
        // load Vi hi+lo, and Vj[cBeg]
#pragma unroll
        for (int j = 0; j < 8; j++) {
            int idx = j * 512 + t, row = idx >> 5, kc = idx & 31;
            unsigned swz = (unsigned)(row * 512) + (((unsigned)kc * 16) ^ (((unsigned)row & 7) << 4));
            cpa16(sb + SE_VIH + swz, vh + (size_t)(base + row) * D_ + kc * 8);
            cpa16(sb + SE_VIL + swz, vl + (size_t)(base + row) * D_ + kc * 8);
        }
        {
            int c0 = base + cBeg * 64;
            unsigned vb = sb + SE_VJ + (unsigned)(cBeg & 1) * 32768u;
#pragma unroll
            for (int j = 0; j < 4; j++) {
                int idx = j * 512 + t, row = idx >> 5, kc = idx & 31;
                unsigned swz = (unsigned)(row * 512) + (((unsigned)kc * 16) ^ (((unsigned)row & 7) << 4));
                cpa16(vb + swz, vh + (size_t)(c0 + row) * D_ + kc * 8);
            }
        }
        CP_COMMIT();

        for (int cc = cBeg; cc < cEnd; cc++) {
            const int c0 = base + cc * 64;
            CP_WAIT0();
            __syncthreads();   // Vj[cc] visible; staging free

            // prefetch Vj[cc+1] (clamped)
            {
                int cnx = (cc + 1 < cEnd) ? cc + 1 : cc;
                int cn0 = base + cnx * 64;
                unsigned vb = sb + SE_VJ + (unsigned)((cc + 1) & 1) * 32768u;
#pragma unroll
                for (int j = 0; j < 4; j++) {
                    int idx = j * 512 + t, row = idx >> 5, kc = idx & 31;
                    unsigned swz = (unsigned)(row * 512) + (((unsigned)kc * 16) ^ (((unsigned)row & 7) << 4));
                    cpa16(vb + swz, vh + (size_t)(cn0 + row) * D_ + kc * 8);
                }
                CP_COMMIT();
            }

            // ---- MMA: S[128x64] = Vi . Vj^T, fp16 2-term (hh + lh) ----
            const unsigned vjb = sb + SE_VJ + (unsigned)(cc & 1) * 32768u;
            float accS[16];
#pragma unroll
            for (int q = 0; q < 16; q++) accS[q] = 0.f;
#pragma unroll
            for (int ks = 0; ks < 16; ks++) {
                unsigned ah[4], al[4], b0[4], b1[4];
                unsigned ka = ((unsigned)(ks * 32) + aK) ^ aSw;
                ldm4(ah, sb + SE_VIH + aBase + ka);
                ldm4(al, sb + SE_VIL + aBase + ka);
                unsigned kb0 = ((unsigned)(ks * 32) + bK) ^ ((bR0 & 7) << 4);
                unsigned kb1 = ((unsigned)(ks * 32) + bK) ^ ((bR1 & 7) << 4);
                ldm4(b0, vjb + bR0 * 512 + kb0);
                ldm4(b1, vjb + bR1 * 512 + kb1);
                mmah(accS + 0,  ah, b0[0], b0[1]);
                mmah(accS + 8,  ah, b1[0], b1[1]);
                mmah(accS + 4,  ah, b0[2], b0[3]);
                mmah(accS + 12, ah, b1[2], b1[3]);
                mmah(accS + 0,  al, b0[0], b0[1]);
                mmah(accS + 8,  al, b1[0], b1[1]);
                mmah(accS + 4,  al, b0[2], b0[3]);
                mmah(accS + 12, al, b1[2], b1[3]);
            }

            // ---- epilogue: softsign -> direct E write (+ staging for mirror) ----
            const bool mirror = (c0 >= base + 128);   // chunk outside diagonal block
#pragma unroll
            for (int q = 0; q < 4; q++) {             // q = sub*2+nf
                int colq = ch * 32 + (q >> 1) * 16 + (q & 1) * 8 + c2;
                float e0 = softsign(accS[q * 4 + 0]);
                float e1 = softsign(accS[q * 4 + 1]);
                float e2 = softsign(accS[q * 4 + 2]);
                float e3 = softsign(accS[q * 4 + 3]);
                unsigned h01 = pack_h2(e0, e1);
                unsigned h23 = pack_h2(e2, e3);
                *reinterpret_cast<unsigned*>(gE + (size_t)(base + RG + r) * N_ + c0 + colq)     = h01;
                *reinterpret_cast<unsigned*>(gE + (size_t)(base + RG + r + 8) * N_ + c0 + colq) = h23;
                if (mirror) {
                    sts32(sb + SE_ES + (unsigned)(RG + r) * 136 + colq * 2, h01);
                    sts32(sb + SE_ES + (unsigned)(RG + r + 8) * 136 + colq * 2, h23);
                }
            }
            if (mirror) {      // block-uniform branch
                __syncthreads();   // staging complete
                // transposed write: warp w handles cols w*4..w*4+3 (two pairs)
#pragma unroll
                for (int jp = 0; jp < 2; jp++) {
                    int cc2 = w * 4 + jp * 2;
#pragma unroll
                    for (int rg4 = 0; rg4 < 4; rg4++) {
                        int rr = rg4 * 32 + lane;
                        unsigned v = lds32(sb + SE_ES + (unsigned)rr * 136 + cc2 * 2);
                        __half2 hv = *(__half2*)&v;
                        gE[(size_t)(c0 + cc2) * N_ + base + rr]     = hv.x;
                        gE[(size_t)(c0 + cc2 + 1) * N_ + base + rr] = hv.y;
                    }
                }
            }
        }
    }
}

// ================= kernel 2: dval = E @ P, dstate = E @ state =================
#define K2_EB 0u        // E double buffer: 2 x (128 rows x 80B)
#define K2_PT 20480u    // Pt double buffer: 2 x (256 rows x 80B)
#define K2_SZ 61440u

__global__ __launch_bounds__(512, 1)
void dval_kernel(const float* __restrict__ state, float* __restrict__ out) {
    extern __shared__ __align__(128) char sm[];
    const unsigned sb = smem_u32(sm);
    const int t = threadIdx.x, lane = t & 31, w = t >> 5;
    const int rg2 = w >> 2, ch2 = w & 3;     // 4 rg2 (m32) x 4 ch2 (e64)
    const int RG2 = rg2 * 32;
    const int b = blockIdx.y;
    const int n0 = blockIdx.x * 128;

    const __half* pth = g_pthi + (size_t)b * D_ * N_;
    const __half* gEb = g_E + (size_t)b * N_ * N_;
    const float* stb = state + b * N_;

    // fragment addresses (same as proven R12 Phase B)
    const unsigned eB0 = (unsigned)(RG2 + (lane & 15)) * 80 + ((unsigned)lane >> 4) * 16;
    const unsigned eB1 = eB0 + 16 * 80;
    const unsigned pB  = ((unsigned)(ch2 * 64) + (((unsigned)lane >> 4) << 3) + (lane & 7)) * 80
                       + (((unsigned)lane >> 3) & 1) * 16;
    const int r = lane >> 2, c = (lane & 3) * 2;

    float accD[64];
#pragma unroll
    for (int q = 0; q < 64; q++) accD[q] = 0.f;
    float ds[4] = {0.f, 0.f, 0.f, 0.f};

    // prologue: E[0], Pt[0] into buf0
    {
        int row = t >> 2, seg = t & 3;
        cpa16(sb + K2_EB + (unsigned)(row * 80 + seg * 16),
              gEb + (size_t)(n0 + row) * N_ + seg * 8);
#pragma unroll
        for (int j = 0; j < 2; j++) {
            int idx = j * 512 + t, prow = idx >> 2, kc = idx & 3;
            cpa16(sb + K2_PT + (unsigned)(prow * 80 + kc * 16),
                  pth + (size_t)prow * N_ + kc * 8);
        }
    }
    CP_COMMIT();

#pragma unroll 1
    for (int i = 0; i < 128; i++) {
        const int m0 = i * 32;
        CP_WAIT0();
        __syncthreads();

        // prefetch m-chunk i+1 (clamped)
        const int m1 = (i < 127) ? m0 + 32 : 0;
        {
            unsigned enx = sb + K2_EB + (unsigned)((i + 1) & 1) * 10240u;
            unsigned pnx = sb + K2_PT + (unsigned)((i + 1) & 1) * 20480u;
            int row = t >> 2, seg = t & 3;
            cpa16(enx + (unsigned)(row * 80 + seg * 16),
                  gEb + (size_t)(n0 + row) * N_ + m1 + seg * 8);
#pragma unroll
            for (int j = 0; j < 2; j++) {
                int idx = j * 512 + t, prow = idx >> 2, kc = idx & 3;
                cpa16(pnx + (unsigned)(prow * 80 + kc * 16),
                      pth + (size_t)prow * N_ + m1 + kc * 8);
            }
            CP_COMMIT();
        }

        const unsigned eb = sb + K2_EB + (unsigned)(i & 1) * 10240u;
        const unsigned pb = sb + K2_PT + (unsigned)(i & 1) * 20480u;
#pragma unroll
        for (int ks = 0; ks < 2; ks++) {
            unsigned eh0[4], eh1[4];
            ldm4(eh0, eb + eB0 + ks * 32);
            ldm4(eh1, eb + eB1 + ks * 32);
            // dstate accumulation (ch2==0 warps own rows exclusively)
            if (ch2 == 0) {
                const int mk = m0 + ks * 16;
                float2 fa = *(const float2*)(stb + mk + c);
                float2 fb = *(const float2*)(stb + mk + c + 8);
                float2 e;
                e = __half22float2(*(__half2*)&eh0[0]); ds[0] += e.x * fa.x + e.y * fa.y;
                e = __half22float2(*(__half2*)&eh0[1]); ds[1] += e.x * fa.x + e.y * fa.y;
                e = __half22float2(*(__half2*)&eh0[2]); ds[0] += e.x * fb.x + e.y * fb.y;
                e = __half22float2(*(__half2*)&eh0[3]); ds[1] += e.x * fb.x + e.y * fb.y;
                e = __half22float2(*(__half2*)&eh1[0]); ds[2] += e.x * fa.x + e.y * fa.y;
                e = __half22float2(*(__half2*)&eh1[1]); ds[3] += e.x * fa.x + e.y * fa.y;
                e = __half22float2(*(__half2*)&eh1[2]); ds[2] += e.x * fb.x + e.y * fb.y;
                e = __half22float2(*(__half2*)&eh1[3]); ds[3] += e.x * fb.x + e.y * fb.y;
            }
#pragma unroll
            for (int g = 0; g < 4; g++) {
                unsigned ph[4];
                unsigned po = pB + (unsigned)(g * 16 * 80 + ks * 32);
                ldm4(ph, pb + po);
                float* d00 = accD + ((0 * 4 + g) * 2 + 0) * 4;
                float* d01 = accD + ((0 * 4 + g) * 2 + 1) * 4;
                float* d10 = accD + ((1 * 4 + g) * 2 + 0) * 4;
                float* d11 = accD + ((1 * 4 + g) * 2 + 1) * 4;
                mmah(d00, eh0, ph[0], ph[1]);
                mmah(d10, eh1, ph[0], ph[1]);
                mmah(d01, eh0, ph[2], ph[3]);
                mmah(d11, eh1, ph[2], ph[3]);
            }
        }
    }

    // -------- write delta_val --------
    float* dvb = out + B_ * N_ + ((size_t)(b * N_ + n0)) * D_;
#pragma unroll
    for (int s = 0; s < 2; s++) {
#pragma unroll
        for (int g = 0; g < 4; g++) {
#pragma unroll
            for (int h2 = 0; h2 < 2; h2++) {
                int row = RG2 + s * 16 + r;
                int col = ch2 * 64 + g * 16 + h2 * 8 + c;
                const float* d = accD + ((s * 4 + g) * 2 + h2) * 4;
                float2 lo; lo.x = d[0]; lo.y = d[1];
                float2 hi; hi.x = d[2]; hi.y = d[3];
                *(float2*)(dvb + (size_t)row * D_ + col) = lo;
                *(float2*)(dvb + (size_t)(row + 8) * D_ + col) = hi;
            }
        }
    }

    // -------- reduce & write delta_state (no atomics; ch2==0 warps own 32 rows each) --------
    if (ch2 == 0) {
#pragma unroll
        for (int j = 0; j < 4; j++) {
            ds[j] += __shfl_xor_sync(0xffffffffu, ds[j], 1);
            ds[j] += __shfl_xor_sync(0xffffffffu, ds[j], 2);
        }
        if ((lane & 3) == 0) {
#pragma unroll
            for (int j = 0; j < 4; j++)
                out[b * N_ + n0 + RG2 + j * 8 + r] = ds[j];
        }
    }
}

extern "C" void kernel_launch(void* const* d_in, const int* in_sizes, int n_in,
                              void* d_out, int out_size) {
    const float* val   = (const float*)d_in[0];  // [B, N, D]
    const float* state = (const float*)d_in[1];  // [B, N]
    const float* Wv    = (const float*)d_in[2];  // [D, D]
    float* out = (float*)d_out;                  // [B*N] delta_state, [B*N*D] delta_val
    (void)in_sizes; (void)n_in; (void)out_size;

    cudaFuncSetAttribute(score_kernel, cudaFuncAttributeMaxDynamicSharedMemorySize, SE_SZ);
    cudaFuncSetAttribute(dval_kernel,  cudaFuncAttributeMaxDynamicSharedMemorySize, K2_SZ);

    split_val<<<(B_ * N_ * D_) / 1024, 256>>>(val);
    proj_kernel<<<dim3(D_ / 64, (B_ * N_) / 64), 256>>>(val, Wv);
    score_kernel<<<dim3(16, 2, 4), 512, SE_SZ>>>();
    dval_kernel<<<dim3(N_ / 128, B_), 512, K2_SZ>>>(state, out);
}

// round 15
// speedup vs baseline: 1.9471x; 1.0409x over previous
#include <cuda_runtime.h>
#include <cuda_fp16.h>

#define B_ 4
#define N_ 4096
#define D_ 256

// Device-global scratch (allocation-free rule)
static __device__ __half  g_vhi[B_ * N_ * D_];      // [b][n][d] fp16 hi
static __device__ __half  g_vlo[B_ * N_ * D_];      // fp16 lo residual
static __device__ __half  g_pthi[B_ * D_ * N_];     // [b][e][m]  P transposed, fp16
static __device__ __half  g_E[(size_t)B_ * N_ * N_];// [b][n][m]  edges, fp16 (134MB)

// ---------------- PTX helpers ----------------
__device__ __forceinline__ unsigned smem_u32(const void* p) {
    unsigned a;
    asm("{ .reg .u64 t; cvta.to.shared.u64 t, %1; cvt.u32.u64 %0, t; }" : "=r"(a) : "l"(p));
    return a;
}
__device__ __forceinline__ void cpa16(unsigned dst, const void* src) {
    asm volatile("cp.async.cg.shared.global [%0], [%1], 16;" :: "r"(dst), "l"(src) : "memory");
}
#define CP_COMMIT() asm volatile("cp.async.commit_group;" ::: "memory")
#define CP_WAIT0()  asm volatile("cp.async.wait_group 0;" ::: "memory")

__device__ __forceinline__ void ldm4(unsigned* r, unsigned addr) {
    asm volatile("ldmatrix.sync.aligned.m8n8.x4.shared.b16 {%0,%1,%2,%3}, [%4];"
                 : "=r"(r[0]), "=r"(r[1]), "=r"(r[2]), "=r"(r[3]) : "r"(addr));
}
__device__ __forceinline__ void mmah(float* d, const unsigned* a, unsigned b0, unsigned b1) {
    asm volatile(
        "mma.sync.aligned.m16n8k16.row.col.f32.f16.f16.f32 "
        "{%0,%1,%2,%3}, {%4,%5,%6,%7}, {%8,%9}, {%0,%1,%2,%3};"
        : "+f"(d[0]), "+f"(d[1]), "+f"(d[2]), "+f"(d[3])
        : "r"(a[0]), "r"(a[1]), "r"(a[2]), "r"(a[3]), "r"(b0), "r"(b1));
}
__device__ __forceinline__ void sts32(unsigned addr, unsigned v) {
    asm volatile("st.shared.u32 [%0], %1;" :: "r"(addr), "r"(v) : "memory");
}
__device__ __forceinline__ unsigned lds32(unsigned addr) {
    unsigned v;
    asm volatile("ld.shared.u32 %0, [%1];" : "=r"(v) : "r"(addr));
    return v;
}
__device__ __forceinline__ unsigned pack_h2(float x, float y) {
    __half2 h; h.x = __float2half_rn(x); h.y = __float2half_rn(y);
    return *(unsigned*)&h;
}
__device__ __forceinline__ float softsign(float s) {
    return __fdividef(s, 1.f + fabsf(s));
}

// ---------------- prologue ----------------
__device__ __forceinline__ unsigned long long ffma2(unsigned long long a,
                                                    unsigned long long b,
                                                    unsigned long long c) {
    unsigned long long d;
    asm("fma.rn.f32x2 %0, %1, %2, %3;" : "=l"(d) : "l"(a), "l"(b), "l"(c));
    return d;
}
__device__ __forceinline__ unsigned long long dup2(float x) {
    unsigned long long d;
    asm("mov.b64 %0, {%1, %1};" : "=l"(d) : "f"(x));
    return d;
}
union V4 { float4 f; unsigned long long u[2]; };

// proj + transpose + fp16 convert fused: writes g_pthi[b][e][m] directly
__global__ __launch_bounds__(256, 2)
void proj_kernel(const float* __restrict__ val, const float* __restrict__ Wv) {
    __shared__ float As[64 * 36];
    __shared__ float Bs[32 * 68];
    __shared__ float Ts[64 * 65];
    const int t = threadIdx.x;
    const int tx = t & 15, ty = t >> 4;
    const int row0 = blockIdx.y * 64;
    const int e0 = blockIdx.x * 64;
    unsigned long long acc[4][2] = {};
    for (int k0 = 0; k0 < D_; k0 += 32) {
#pragma unroll
        for (int p = 0; p < 2; p++) {
            int idx = p * 256 + t, r = idx >> 3, q = idx & 7;
            *(float4*)&As[r * 36 + q * 4] =
                *(const float4*)&val[(size_t)(row0 + r) * D_ + k0 + q * 4];
        }
#pragma unroll
        for (int p = 0; p < 2; p++) {
            int idx = p * 256 + t, kr = idx >> 4, ec = idx & 15;
            *(float4*)&Bs[kr * 68 + ec * 4] =
                *(const float4*)&Wv[(k0 + kr) * D_ + e0 + ec * 4];
        }
        __syncthreads();
#pragma unroll 16
        for (int kk = 0; kk < 32; kk++) {
            V4 bv; bv.f = *(float4*)&Bs[kk * 68 + tx * 4];
#pragma unroll
            for (int i = 0; i < 4; i++) {
                unsigned long long a2 = dup2(As[(ty * 4 + i) * 36 + kk]);
                acc[i][0] = ffma2(a2, bv.u[0], acc[i][0]);
                acc[i][1] = ffma2(a2, bv.u[1], acc[i][1]);
            }
        }
        __syncthreads();
    }
#pragma unroll
    for (int i = 0; i < 4; i++) {
        V4 o; o.u[0] = acc[i][0]; o.u[1] = acc[i][1];
        float v4[4] = {o.f.x, o.f.y, o.f.z, o.f.w};
#pragma unroll
        for (int q = 0; q < 4; q++)
            Ts[(tx * 4 + q) * 65 + ty * 4 + i] = v4[q];
    }
    __syncthreads();
    {
        const int b = row0 >> 12, m0l = row0 & (N_ - 1);
        const int e_l = t >> 2, ms = (t & 3) * 16;
        unsigned hw[8];
#pragma unroll
        for (int jj = 0; jj < 8; jj++)
            hw[jj] = pack_h2(Ts[e_l * 65 + ms + 2 * jj], Ts[e_l * 65 + ms + 2 * jj + 1]);
        size_t o = ((size_t)(b * D_ + e0 + e_l)) * N_ + m0l + ms;
        *(uint4*)(g_pthi + o)     = make_uint4(hw[0], hw[1], hw[2], hw[3]);
        *(uint4*)(g_pthi + o + 8) = make_uint4(hw[4], hw[5], hw[6], hw[7]);
    }
}

__global__ __launch_bounds__(256)
void split_val(const float* __restrict__ val) {
    size_t i = ((size_t)blockIdx.x * 256 + threadIdx.x) * 4;
    float4 v = *(const float4*)(val + i);
    float a[4] = {v.x, v.y, v.z, v.w};
#pragma unroll
    for (int k = 0; k < 4; k += 2) {
        __half h0 = __float2half_rn(a[k]);
        __half h1 = __float2half_rn(a[k + 1]);
        __half2 hp; hp.x = h0; hp.y = h1;
        __half2 lp;
        lp.x = __float2half_rn(a[k] - __half2float(h0));
        lp.y = __float2half_rn(a[k + 1] - __half2float(h1));
        *(__half2*)(g_vhi + i + k) = hp;
        *(__half2*)(g_vlo + i + k) = lp;
    }
}

// ================= kernel 1: scores -> E (upper triangle + mirror) =================
// grid (16 pairs, 2 j-halves, 4 batches) = 128 CTAs, 512 threads.
#define SE_VIH 0u          // Vi_hi 128 x 512B swizzled
#define SE_VIL 65536u      // Vi_lo
#define SE_VJ  131072u     // Vj_hi double buffer 2 x 32768 (64 rows x 512B)
#define SE_ES  196608u     // E staging 128 x 136B
#define SE_SZ  214016u

__global__ __launch_bounds__(512, 1)
void score_kernel() {
    extern __shared__ __align__(128) char sm[];
    const unsigned sb = smem_u32(sm);
    const int t = threadIdx.x, lane = t & 31, w = t >> 5;
    const int rg = w >> 1, ch = w & 1;       // 8 rg (m16) x 2 ch (n32)
    const int RG = rg * 16;
    const int p = blockIdx.x, hh = blockIdx.y, b = blockIdx.z;
    const __half* vh = g_vhi + (size_t)b * N_ * D_;
    const __half* vl = g_vlo + (size_t)b * N_ * D_;
    __half* gE = g_E + (size_t)b * N_ * N_;

    const unsigned aRow = RG + (lane & 15);
    const unsigned aK   = ((unsigned)lane >> 4) * 16;
    const unsigned aSw  = (aRow & 7) << 4;
    const unsigned aBase = aRow * 512;
    const unsigned bR0 = (unsigned)(ch * 32) + (((unsigned)lane >> 4) << 3) + (lane & 7);
    const unsigned bR1 = bR0 + 16;
    const unsigned bK  = (((unsigned)lane >> 3) & 1) * 16;
    const int r = lane >> 2, c2 = (lane & 3) * 2;

    for (int phase = 0; phase < 2; phase++) {
        const int bi = phase ? 31 - p : p;
        const int half_cnt = 32 - bi;
        const int cBeg = hh * half_cnt;
        const int cEnd = cBeg + half_cnt;
        const int base = 128 * bi;

        __syncthreads();
#pragma unroll
        for (int j = 0; j < 8; j++) {
            int idx = j * 512 + t, row = idx >> 5, kc = idx & 31;
            unsigned swz = (unsigned)(row * 512) + (((unsigned)kc * 16) ^ (((unsigned)row & 7) << 4));
            cpa16(sb + SE_VIH + swz, vh + (size_t)(base + row) * D_ + kc * 8);
            cpa16(sb + SE_VIL + swz, vl + (size_t)(base + row) * D_ + kc * 8);
        }
        {
            int c0 = base + cBeg * 64;
            unsigned vb = sb + SE_VJ + (unsigned)(cBeg & 1) * 32768u;
#pragma unroll
            for (int j = 0; j < 4; j++) {
                int idx = j * 512 + t, row = idx >> 5, kc = idx & 31;
                unsigned swz = (unsigned)(row * 512) + (((unsigned)kc * 16) ^ (((unsigned)row & 7) << 4));
                cpa16(vb + swz, vh + (size_t)(c0 + row) * D_ + kc * 8);
            }
        }
        CP_COMMIT();

        for (int cc = cBeg; cc < cEnd; cc++) {
            const int c0 = base + cc * 64;
            CP_WAIT0();
            __syncthreads();

            {
                int cnx = (cc + 1 < cEnd) ? cc + 1 : cc;
                int cn0 = base + cnx * 64;
                unsigned vb = sb + SE_VJ + (unsigned)((cc + 1) & 1) * 32768u;
#pragma unroll
                for (int j = 0; j < 4; j++) {
                    int idx = j * 512 + t, row = idx >> 5, kc = idx & 31;
                    unsigned swz = (unsigned)(row * 512) + (((unsigned)kc * 16) ^ (((unsigned)row & 7) << 4));
                    cpa16(vb + swz, vh + (size_t)(cn0 + row) * D_ + kc * 8);
                }
                CP_COMMIT();
            }

            const unsigned vjb = sb + SE_VJ + (unsigned)(cc & 1) * 32768u;
            float accS[16];
#pragma unroll
            for (int q = 0; q < 16; q++) accS[q] = 0.f;
#pragma unroll
            for (int ks = 0; ks < 16; ks++) {
                unsigned ah[4], al[4], b0[4], b1[4];
                unsigned ka = ((unsigned)(ks * 32) + aK) ^ aSw;
                ldm4(ah, sb + SE_VIH + aBase + ka);
                ldm4(al, sb + SE_VIL + aBase + ka);
                unsigned kb0 = ((unsigned)(ks * 32) + bK) ^ ((bR0 & 7) << 4);
                unsigned kb1 = ((unsigned)(ks * 32) + bK) ^ ((bR1 & 7) << 4);
                ldm4(b0, vjb + bR0 * 512 + kb0);
                ldm4(b1, vjb + bR1 * 512 + kb1);
                mmah(accS + 0,  ah, b0[0], b0[1]);
                mmah(accS + 8,  ah, b1[0], b1[1]);
                mmah(accS + 4,  ah, b0[2], b0[3]);
                mmah(accS + 12, ah, b1[2], b1[3]);
                mmah(accS + 0,  al, b0[0], b0[1]);
                mmah(accS + 8,  al, b1[0], b1[1]);
                mmah(accS + 4,  al, b0[2], b0[3]);
                mmah(accS + 12, al, b1[2], b1[3]);
            }

            const bool mirror = (c0 >= base + 128);
#pragma unroll
            for (int q = 0; q < 4; q++) {
                int colq = ch * 32 + (q >> 1) * 16 + (q & 1) * 8 + c2;
                float e0 = softsign(accS[q * 4 + 0]);
                float e1 = softsign(accS[q * 4 + 1]);
                float e2 = softsign(accS[q * 4 + 2]);
                float e3 = softsign(accS[q * 4 + 3]);
                unsigned h01 = pack_h2(e0, e1);
                unsigned h23 = pack_h2(e2, e3);
                *reinterpret_cast<unsigned*>(gE + (size_t)(base + RG + r) * N_ + c0 + colq)     = h01;
                *reinterpret_cast<unsigned*>(gE + (size_t)(base + RG + r + 8) * N_ + c0 + colq) = h23;
                if (mirror) {
                    sts32(sb + SE_ES + (unsigned)(RG + r) * 136 + colq * 2, h01);
                    sts32(sb + SE_ES + (unsigned)(RG + r + 8) * 136 + colq * 2, h23);
                }
            }
            if (mirror) {
                __syncthreads();
#pragma unroll
                for (int jp = 0; jp < 2; jp++) {
                    int cc2 = w * 4 + jp * 2;
#pragma unroll
                    for (int rg4 = 0; rg4 < 4; rg4++) {
                        int rr = rg4 * 32 + lane;
                        unsigned v = lds32(sb + SE_ES + (unsigned)rr * 136 + cc2 * 2);
                        __half2 hv = *(__half2*)&v;
                        gE[(size_t)(c0 + cc2) * N_ + base + rr]     = hv.x;
                        gE[(size_t)(c0 + cc2 + 1) * N_ + base + rr] = hv.y;
                    }
                }
            }
        }
    }
}

// ================= kernel 2: dval = E @ P, dstate = E @ state =================
// 256 threads / 8 warps, n-tile 64 rows, grid (64, 4) = 256 CTAs, 2 CTAs/SM.
#define K2_EB 0u        // E double buffer: 2 x (64 rows x 80B) = 10240
#define K2_PT 10240u    // Pt double buffer: 2 x (256 rows x 80B) = 40960
#define K2_SZ 51200u

__global__ __launch_bounds__(256, 2)
void dval_kernel(const float* __restrict__ state, float* __restrict__ out) {
    extern __shared__ __align__(128) char sm[];
    const unsigned sb = smem_u32(sm);
    const int t = threadIdx.x, lane = t & 31, w = t >> 5;
    const int rg2 = w >> 2, ch2 = w & 3;     // 2 rg2 (m32) x 4 ch2 (e64)
    const int RG2 = rg2 * 32;
    const int b = blockIdx.y;
    const int n0 = blockIdx.x * 64;

    const __half* pth = g_pthi + (size_t)b * D_ * N_;
    const __half* gEb = g_E + (size_t)b * N_ * N_;
    const float* stb = state + b * N_;

    // fragment addresses (proven R12/R14 Phase-B layout, 64-row E buffer)
    const unsigned eB0 = (unsigned)(RG2 + (lane & 15)) * 80 + ((unsigned)lane >> 4) * 16;
    const unsigned eB1 = eB0 + 16 * 80;
    const unsigned pB  = ((unsigned)(ch2 * 64) + (((unsigned)lane >> 4) << 3) + (lane & 7)) * 80
                       + (((unsigned)lane >> 3) & 1) * 16;
    const int r = lane >> 2, c = (lane & 3) * 2;

    float accD[64];
#pragma unroll
    for (int q = 0; q < 64; q++) accD[q] = 0.f;
    float ds[4] = {0.f, 0.f, 0.f, 0.f};

    // prologue: E[0] (64x32), Pt[0] (256x32) into buf0
    {
        int row = t >> 2, seg = t & 3;
        cpa16(sb + K2_EB + (unsigned)(row * 80 + seg * 16),
              gEb + (size_t)(n0 + row) * N_ + seg * 8);
#pragma unroll
        for (int j = 0; j < 4; j++) {
            int idx = j * 256 + t, prow = idx >> 2, kc = idx & 3;
            cpa16(sb + K2_PT + (unsigned)(prow * 80 + kc * 16),
                  pth + (size_t)prow * N_ + kc * 8);
        }
    }
    CP_COMMIT();

#pragma unroll 1
    for (int i = 0; i < 128; i++) {
        const int m0 = i * 32;
        CP_WAIT0();
        __syncthreads();

        // prefetch m-chunk i+1 (clamped)
        const int m1 = (i < 127) ? m0 + 32 : 0;
        {
            unsigned enx = sb + K2_EB + (unsigned)((i + 1) & 1) * 5120u;
            unsigned pnx = sb + K2_PT + (unsigned)((i + 1) & 1) * 20480u;
            int row = t >> 2, seg = t & 3;
            cpa16(enx + (unsigned)(row * 80 + seg * 16),
                  gEb + (size_t)(n0 + row) * N_ + m1 + seg * 8);
#pragma unroll
            for (int j = 0; j < 4; j++) {
                int idx = j * 256 + t, prow = idx >> 2, kc = idx & 3;
                cpa16(pnx + (unsigned)(prow * 80 + kc * 16),
                      pth + (size_t)prow * N_ + m1 + kc * 8);
            }
            CP_COMMIT();
        }

        const unsigned eb = sb + K2_EB + (unsigned)(i & 1) * 5120u;
        const unsigned pb = sb + K2_PT + (unsigned)(i & 1) * 20480u;
#pragma unroll
        for (int ks = 0; ks < 2; ks++) {
            unsigned eh0[4], eh1[4];
            ldm4(eh0, eb + eB0 + ks * 32);
            ldm4(eh1, eb + eB1 + ks * 32);
            // dstate accumulation (ch2==0 warps own rows exclusively)
            if (ch2 == 0) {
                const int mk = m0 + ks * 16;
                float2 fa = *(const float2*)(stb + mk + c);
                float2 fb = *(const float2*)(stb + mk + c + 8);
                float2 e;
                e = __half22float2(*(__half2*)&eh0[0]); ds[0] += e.x * fa.x + e.y * fa.y;
                e = __half22float2(*(__half2*)&eh0[1]); ds[1] += e.x * fa.x + e.y * fa.y;
                e = __half22float2(*(__half2*)&eh0[2]); ds[0] += e.x * fb.x + e.y * fb.y;
                e = __half22float2(*(__half2*)&eh0[3]); ds[1] += e.x * fb.x + e.y * fb.y;
                e = __half22float2(*(__half2*)&eh1[0]); ds[2] += e.x * fa.x + e.y * fa.y;
                e = __half22float2(*(__half2*)&eh1[1]); ds[3] += e.x * fa.x + e.y * fa.y;
                e = __half22float2(*(__half2*)&eh1[2]); ds[2] += e.x * fb.x + e.y * fb.y;
                e = __half22float2(*(__half2*)&eh1[3]); ds[3] += e.x * fb.x + e.y * fb.y;
            }
#pragma unroll
            for (int g = 0; g < 4; g++) {
                unsigned ph[4];
                unsigned po = pB + (unsigned)(g * 16 * 80 + ks * 32);
                ldm4(ph, pb + po);
                float* d00 = accD + ((0 * 4 + g) * 2 + 0) * 4;
                float* d01 = accD + ((0 * 4 + g) * 2 + 1) * 4;
                float* d10 = accD + ((1 * 4 + g) * 2 + 0) * 4;
                float* d11 = accD + ((1 * 4 + g) * 2 + 1) * 4;
                mmah(d00, eh0, ph[0], ph[1]);
                mmah(d10, eh1, ph[0], ph[1]);
                mmah(d01, eh0, ph[2], ph[3]);
                mmah(d11, eh1, ph[2], ph[3]);
            }
        }
    }

    // -------- write delta_val --------
    float* dvb = out + B_ * N_ + ((size_t)(b * N_ + n0)) * D_;
#pragma unroll
    for (int s = 0; s < 2; s++) {
#pragma unroll
        for (int g = 0; g < 4; g++) {
#pragma unroll
            for (int h2 = 0; h2 < 2; h2++) {
                int row = RG2 + s * 16 + r;
                int col = ch2 * 64 + g * 16 + h2 * 8 + c;
                const float* d = accD + ((s * 4 + g) * 2 + h2) * 4;
                float2 lo; lo.x = d[0]; lo.y = d[1];
                float2 hi; hi.x = d[2]; hi.y = d[3];
                *(float2*)(dvb + (size_t)row * D_ + col) = lo;
                *(float2*)(dvb + (size_t)(row + 8) * D_ + col) = hi;
            }
        }
    }

    // -------- reduce & write delta_state (no atomics; ch2==0 warps own 32 rows each) --------
    if (ch2 == 0) {
#pragma unroll
        for (int j = 0; j < 4; j++) {
            ds[j] += __shfl_xor_sync(0xffffffffu, ds[j], 1);
            ds[j] += __shfl_xor_sync(0xffffffffu, ds[j], 2);
        }
        if ((lane & 3) == 0) {
#pragma unroll
            for (int j = 0; j < 4; j++)
                out[b * N_ + n0 + RG2 + j * 8 + r] = ds[j];
        }
    }
}

extern "C" void kernel_launch(void* const* d_in, const int* in_sizes, int n_in,
                              void* d_out, int out_size) {
    const float* val   = (const float*)d_in[0];  // [B, N, D]
    const float* state = (const float*)d_in[1];  // [B, N]
    const float* Wv    = (const float*)d_in[2];  // [D, D]
    float* out = (float*)d_out;                  // [B*N] delta_state, [B*N*D] delta_val
    (void)in_sizes; (void)n_in; (void)out_size;

    cudaFuncSetAttribute(score_kernel, cudaFuncAttributeMaxDynamicSharedMemorySize, SE_SZ);
    cudaFuncSetAttribute(dval_kernel,  cudaFuncAttributeMaxDynamicSharedMemorySize, K2_SZ);

    split_val<<<(B_ * N_ * D_) / 1024, 256>>>(val);
    proj_kernel<<<dim3(D_ / 64, (B_ * N_) / 64), 256>>>(val, Wv);
    score_kernel<<<dim3(16, 2, 4), 512, SE_SZ>>>();
    dval_kernel<<<dim3(N_ / 64, B_), 256, K2_SZ>>>(state, out);
}